// round 2
// baseline (speedup 1.0000x reference)
#include <cuda_runtime.h>
#include <cstdint>
#include <math.h>

#define N_SAMP 4096
#define D      128
#define NLAY   5
#define NCU    23          // used Taylor coefficients per neuron
#define NCP    24          // padded
#define SPC    8           // samples per CTA (main)
#define ROWS   (SPC*NCP)   // 192
#define SSTR   132         // shared row stride (floats)
#define NTHR   256
#define RT     12          // rows per thread
#define CT     8           // cols per thread

#define SB     64          // samples per CTA (boundary)
#define BSTR   132

#define TWO_PI 6.2831853071795864769f
#define PI_F   3.1415926535897932385f
#define C2     19.739208802178717238f     /* 2*pi^2  */
#define C3     124.02510672119926149f     /* 4*pi^3  */
#define S_CONST 8.3666002653407556e-04f   /* sqrt(0.7/1e6)   */
#define KAPPA   1.1952286093343936e-03f   /* sqrt(1/7e5)     */

// ---------------- scratch (device globals; no allocation) ----------------
__device__ float g_xy[2*N_SAMP];
__device__ float g_zb[N_SAMP];
__device__ float g_part[(N_SAMP/SPC)*4];   // per-CTA: data, conti, nse, ee
__device__ float g_tbpart[N_SAMP/SB];

// ---------------- threefry2x32-20 (exact JAX) ----------------
__device__ __forceinline__ void tf2(uint32_t k0, uint32_t k1,
                                    uint32_t x0, uint32_t x1,
                                    uint32_t& o0, uint32_t& o1) {
    uint32_t ks2 = k0 ^ k1 ^ 0x1BD11BDAu;
    x0 += k0; x1 += k1;
#define TF_R(r) { x0 += x1; x1 = (x1 << (r)) | (x1 >> (32-(r))); x1 ^= x0; }
    TF_R(13) TF_R(15) TF_R(26) TF_R(6)
    x0 += k1;  x1 += ks2 + 1u;
    TF_R(17) TF_R(29) TF_R(16) TF_R(24)
    x0 += ks2; x1 += k0 + 2u;
    TF_R(13) TF_R(15) TF_R(26) TF_R(6)
    x0 += k0;  x1 += k1 + 3u;
    TF_R(17) TF_R(29) TF_R(16) TF_R(24)
    x0 += k1;  x1 += ks2 + 4u;
    TF_R(13) TF_R(15) TF_R(26) TF_R(6)
    x0 += ks2; x1 += k0 + 5u;
#undef TF_R
    o0 = x0; o1 = x1;
}

__device__ __forceinline__ float u01(uint32_t bits) {
    return __uint_as_float((bits >> 9) | 0x3F800000u) - 1.0f;
}

__global__ void pinn_rng() {
    int i = blockIdx.x * blockDim.x + threadIdx.x;     // 0..4095
    uint32_t a0, a1, b0, b1;
    tf2(0u, 22u, 0u, 2u, a0, a1);   // split(key(22)) lane 0
    tf2(0u, 22u, 1u, 3u, b0, b1);   // lane 1
    // kb1 = (a0,b0), kb2 = (a1,b1)
    uint32_t o0, o1;
    tf2(a0, b0, (uint32_t)i, (uint32_t)(i + 4096), o0, o1);
    g_xy[i]        = u01(o0);
    g_xy[i + 4096] = u01(o1);
    if (i < 2048) {
        uint32_t r0, r1;
        tf2(a1, b1, (uint32_t)i, (uint32_t)(i + 2048), r0, r1);
        g_zb[i]        = (float)(r0 & 1u);
        g_zb[i + 2048] = (float)(r1 & 1u);
    }
}

// ---------------- activation jet propagation ----------------
// coeffs: 0=val, 1..4 = d/dx_i (i=0..3),
// 5..13 second derivs: (0,1),(0,2),(0,3),(1,1),(1,2),(1,3),(2,2),(2,3),(3,3)
// 14..22 third derivs {a,b,b}: (a,b) = (1,1),(2,1),(3,1),(1,2),(2,2),(3,2),(1,3),(2,3),(3,3)
__device__ __forceinline__ void act_prop(float z[NCU]) {
    const int p2a[9] = {0,0,0,1,1,1,2,2,3};
    const int p2b[9] = {1,2,3,1,2,3,2,3,3};
    const int t3a[9] = {1,2,3,1,2,3,1,2,3};
    const int t3b[9] = {1,1,1,2,2,2,3,3,3};
    const int s2s[4][4] = { {0,0,1,2}, {0,3,4,5}, {1,4,6,7}, {2,5,7,8} }; // slot in d2 ([0][0] unused)

    float sv, cv;
    sincosf(TWO_PI * z[0], &sv, &cv);
    float f0 = 0.5f * sv;
    float f1 = PI_F * cv;
    float f2 = -C2 * sv;
    float f3 = -C3 * cv;

    float d1[4], d2[9], d3[9];
#pragma unroll
    for (int i = 0; i < 4; i++) d1[i] = z[1+i];
#pragma unroll
    for (int p = 0; p < 9; p++) d2[p] = z[5+p];
#pragma unroll
    for (int q = 0; q < 9; q++) d3[q] = z[14+q];

    z[0] = f0;
#pragma unroll
    for (int i = 0; i < 4; i++) z[1+i] = f1 * d1[i];
#pragma unroll
    for (int p = 0; p < 9; p++)
        z[5+p] = f1 * d2[p] + f2 * d1[p2a[p]] * d1[p2b[p]];
#pragma unroll
    for (int q = 0; q < 9; q++) {
        int a = t3a[q], b = t3b[q];
        float zbb = d2[s2s[b][b]];
        float zab = d2[s2s[a][b]];
        z[14+q] = f1 * d3[q]
                + f2 * (d1[a]*zbb + 2.0f*d1[b]*zab)
                + f3 * d1[a]*d1[b]*d1[b];
    }
}

// ---------------- main jet-propagation kernel ----------------
__global__ void __launch_bounds__(NTHR, 1)
pinn_main(const float* __restrict__ inputs, const float* __restrict__ y_true,
          const float* __restrict__ Win, const float* __restrict__ bin,
          const float* __restrict__ Wh,  const float* __restrict__ bh,
          const float* __restrict__ Wo,  const float* __restrict__ bo)
{
    extern __shared__ float sm[];
    float* sS  = sm;                     // ROWS*SSTR
    float* sW  = sm + ROWS*SSTR;         // D*D
    float* sx  = sW + D*D;               // 32 floats
    float* sls = sx + 32;                // 8*4 partial losses
    float* yc  = sW;                     // reuse after GEMMs (8*23*4 floats)

    int tid = threadIdx.x;
    int blk = blockIdx.x;
    int s0  = blk * SPC;

    if (tid < SPC*4) sx[tid] = inputs[s0*4 + tid];
    __syncthreads();

    // ---- layer 0: x @ W_in + b_in, init jet, activate ----
    for (int p = tid; p < SPC*D; p += NTHR) {
        int s = p >> 7, n = p & 127;
        float z[NCU];
        float zv = bin[n];
#pragma unroll
        for (int k = 0; k < 4; k++) zv += sx[s*4+k] * Win[k*D+n];
        z[0] = zv;
#pragma unroll
        for (int i = 0; i < 4; i++) z[1+i] = Win[i*D+n];
#pragma unroll
        for (int c = 5; c < NCU; c++) z[c] = 0.0f;
        act_prop(z);
        int rb = (s*NCP)*SSTR + n;
#pragma unroll
        for (int c = 0; c < NCU; c++) sS[rb + c*SSTR] = z[c];
        sS[rb + 23*SSTR] = 0.0f;   // pad row
    }

    int ry = tid >> 4, cx = tid & 15;
    int row0 = ry * RT, col0 = cx * CT;

    // ---- 5 hidden layers ----
    for (int l = 0; l < NLAY; l++) {
        __syncthreads();
        { // load weights
            const float4* Wg = (const float4*)(Wh + l*D*D);
            float4* sW4 = (float4*)sW;
            for (int i = tid; i < D*D/4; i += NTHR) sW4[i] = Wg[i];
        }
        __syncthreads();

        float acc[RT][CT];
#pragma unroll
        for (int i = 0; i < RT; i++)
#pragma unroll
            for (int j = 0; j < CT; j++) acc[i][j] = 0.0f;

        for (int k = 0; k < D; k += 4) {
            float a[RT][4];
#pragma unroll
            for (int i = 0; i < RT; i++) {
                float4 t = *(const float4*)&sS[(row0+i)*SSTR + k];
                a[i][0]=t.x; a[i][1]=t.y; a[i][2]=t.z; a[i][3]=t.w;
            }
#pragma unroll
            for (int kk = 0; kk < 4; kk++) {
                float b[CT];
                float4 t0 = *(const float4*)&sW[(k+kk)*D + col0];
                float4 t1 = *(const float4*)&sW[(k+kk)*D + col0 + 4];
                b[0]=t0.x; b[1]=t0.y; b[2]=t0.z; b[3]=t0.w;
                b[4]=t1.x; b[5]=t1.y; b[6]=t1.z; b[7]=t1.w;
#pragma unroll
                for (int i = 0; i < RT; i++)
#pragma unroll
                    for (int j = 0; j < CT; j++)
                        acc[i][j] += a[i][kk] * b[j];
            }
        }
        __syncthreads();   // all GEMM reads of sS done
#pragma unroll
        for (int i = 0; i < RT; i++)
#pragma unroll
            for (int j = 0; j < CT; j++)
                sS[(row0+i)*SSTR + col0 + j] = acc[i][j];
        __syncthreads();

        // activation (adds bias to value coeff)
        for (int p = tid; p < SPC*D; p += NTHR) {
            int s = p >> 7, n = p & 127;
            float z[NCU];
            int rb = (s*NCP)*SSTR + n;
#pragma unroll
            for (int c = 0; c < NCU; c++) z[c] = sS[rb + c*SSTR];
            z[0] += bh[l*D + n];
            act_prop(z);
#pragma unroll
            for (int c = 0; c < NCU; c++) sS[rb + c*SSTR] = z[c];
        }
    }
    __syncthreads();

    // ---- output layer: yc[s][c][o] = h[s][c][:] . Wo[:,o] (+bias on value) ----
    for (int p = tid; p < SPC*NCU*4; p += NTHR) {
        int s = p / (NCU*4);
        int r = p % (NCU*4);
        int c = r >> 2, o = r & 3;
        float sum = (c == 0) ? bo[o] : 0.0f;
        const float* hr = &sS[(s*NCP + c)*SSTR];
        for (int n = 0; n < D; n++) sum += hr[n] * Wo[n*4 + o];
        yc[(s*NCU + c)*4 + o] = sum;
    }
    __syncthreads();

    // ---- per-sample losses ----
    if (tid < SPC) {
        const int s = tid;
        const int s2c[4][4] = { {0,5,6,7}, {5,8,9,10}, {6,9,11,12}, {7,10,12,13} };
        auto YC = [&](int c, int o) { return yc[(s*NCU + c)*4 + o]; };
        auto Hc = [&](int o, int i, int j) { return YC(s2c[i][j], o); };
        auto Gc = [&](int o, int a, int b) { return YC(14 + (b-1)*3 + (a-1), o); };
        auto J  = [&](int o, int i) { return YC(1+i, o); };

        float u = YC(0,0), v = YC(0,1), w = YC(0,2);
        float u_x=J(0,1), u_y=J(0,2), u_z=J(0,3);
        float v_x=J(1,1), v_y=J(1,2), v_z=J(1,3);
        float w_x=J(2,1), w_y=J(2,2), w_z=J(2,3);
        float T_t=J(3,0), T_x=J(3,1), T_y=J(3,2), T_z=J(3,3);

        float om_x = w_y - v_z, om_y = u_z - w_x, om_z = v_x - u_y;

        float NSE_u = Hc(2,2,0) - Hc(1,3,0)
                    + u*(Hc(2,2,1)-Hc(1,3,1)) + v*(Hc(2,2,2)-Hc(1,3,2)) + w*(Hc(2,2,3)-Hc(1,3,3))
                    - om_x*u_x - om_y*u_y - om_z*u_z
                    - S_CONST*( Gc(2,2,1)-Gc(1,3,1) + Gc(2,2,2)-Gc(1,3,2) + Gc(2,2,3)-Gc(1,3,3) )
                    - T_y;
        float NSE_v = Hc(0,3,0) - Hc(2,1,0)
                    + u*(Hc(0,3,1)-Hc(2,1,1)) + v*(Hc(0,3,2)-Hc(2,1,2)) + w*(Hc(0,3,3)-Hc(2,1,3))
                    - om_x*v_x - om_y*v_y - om_z*v_z
                    - S_CONST*( Gc(0,3,1)-Gc(2,1,1) + Gc(0,3,2)-Gc(2,1,2) + Gc(0,3,3)-Gc(2,1,3) )
                    + T_x;
        float NSE_w = Hc(1,1,0) - Hc(0,2,0)
                    + u*(Hc(1,1,1)-Hc(0,2,1)) + v*(Hc(1,1,2)-Hc(0,2,2)) + w*(Hc(1,1,3)-Hc(0,2,3))
                    - om_x*w_x - om_y*w_y - om_z*w_z
                    - S_CONST*( Gc(1,1,1)-Gc(0,2,1) + Gc(1,1,2)-Gc(0,2,2) + Gc(1,1,3)-Gc(0,2,3) );
        float EE = T_t + u*T_x + v*T_y + w*T_z
                 - KAPPA*( Hc(3,1,1) + Hc(3,2,2) + Hc(3,3,3) );

        float ld = 0.0f;
#pragma unroll
        for (int o = 0; o < 3; o++) {
            float d = YC(0,o) - y_true[(s0+s)*4 + o];
            ld += d*d;
        }
        float conti = u_x + v_y + w_z;
        sls[s*4+0] = ld;
        sls[s*4+1] = conti*conti;
        sls[s*4+2] = NSE_u*NSE_u + NSE_v*NSE_v + NSE_w*NSE_w;
        sls[s*4+3] = EE*EE;
    }
    __syncthreads();
    if (tid == 0) {
        float a0=0, a1=0, a2=0, a3=0;
        for (int s = 0; s < SPC; s++) {
            a0 += sls[s*4+0]; a1 += sls[s*4+1];
            a2 += sls[s*4+2]; a3 += sls[s*4+3];
        }
        g_part[blk*4+0] = a0; g_part[blk*4+1] = a1;
        g_part[blk*4+2] = a2; g_part[blk*4+3] = a3;
    }
}

// ---------------- boundary batch (value-only propagation) ----------------
__global__ void __launch_bounds__(256, 1)
pinn_bound(const float* __restrict__ inputs,
           const float* __restrict__ Win, const float* __restrict__ bin,
           const float* __restrict__ Wh,  const float* __restrict__ bh,
           const float* __restrict__ Wo,  const float* __restrict__ bo)
{
    extern __shared__ float sm[];
    float* sH  = sm;                // SB*BSTR
    float* sW  = sm + SB*BSTR;      // D*D
    float* red = sW + D*D;          // 256

    int tid = threadIdx.x;
    int blk = blockIdx.x;
    int s0 = blk * SB;

    for (int p = tid; p < SB*D; p += 256) {
        int s = p >> 7, n = p & 127;
        int gs = s0 + s;
        float t  = inputs[gs*4];
        float xb = g_xy[2*gs], yb = g_xy[2*gs+1], zb = g_zb[gs];
        float z = bin[n] + t*Win[n] + xb*Win[D+n] + yb*Win[2*D+n] + zb*Win[3*D+n];
        sH[s*BSTR + n] = 0.5f * sinf(TWO_PI * z);
    }

    int ry = tid >> 4, cx = tid & 15;
    int row0 = ry * 4, col0 = cx * 8;

    for (int l = 0; l < NLAY; l++) {
        __syncthreads();
        {
            const float4* Wg = (const float4*)(Wh + l*D*D);
            float4* sW4 = (float4*)sW;
            for (int i = tid; i < D*D/4; i += 256) sW4[i] = Wg[i];
        }
        __syncthreads();

        float acc[4][8];
#pragma unroll
        for (int i = 0; i < 4; i++)
#pragma unroll
            for (int j = 0; j < 8; j++) acc[i][j] = 0.0f;

        for (int k = 0; k < D; k += 4) {
            float a[4][4];
#pragma unroll
            for (int i = 0; i < 4; i++) {
                float4 t = *(const float4*)&sH[(row0+i)*BSTR + k];
                a[i][0]=t.x; a[i][1]=t.y; a[i][2]=t.z; a[i][3]=t.w;
            }
#pragma unroll
            for (int kk = 0; kk < 4; kk++) {
                float b[8];
                float4 t0 = *(const float4*)&sW[(k+kk)*D + col0];
                float4 t1 = *(const float4*)&sW[(k+kk)*D + col0 + 4];
                b[0]=t0.x; b[1]=t0.y; b[2]=t0.z; b[3]=t0.w;
                b[4]=t1.x; b[5]=t1.y; b[6]=t1.z; b[7]=t1.w;
#pragma unroll
                for (int i = 0; i < 4; i++)
#pragma unroll
                    for (int j = 0; j < 8; j++)
                        acc[i][j] += a[i][kk] * b[j];
            }
        }
        __syncthreads();
#pragma unroll
        for (int i = 0; i < 4; i++)
#pragma unroll
            for (int j = 0; j < 8; j++)
                sH[(row0+i)*BSTR + col0 + j] = acc[i][j];
        __syncthreads();
        for (int p = tid; p < SB*D; p += 256) {
            int s = p >> 7, n = p & 127;
            float z = sH[s*BSTR + n] + bh[l*D + n];
            sH[s*BSTR + n] = 0.5f * sinf(TWO_PI * z);
        }
    }
    __syncthreads();

    {   // T = h . Wo[:,3] + bo[3]
        int s = tid & 63, q = tid >> 6;
        float part = 0.0f;
        for (int n = q*32; n < q*32 + 32; n++)
            part += sH[s*BSTR + n] * Wo[n*4 + 3];
        red[tid] = part;
    }
    __syncthreads();
    if (tid < 64) {
        float T = red[tid] + red[tid+64] + red[tid+128] + red[tid+192] + bo[3];
        float Tt = (g_zb[s0 + tid] == 0.0f) ? 0.5f : -0.5f;
        float d = Tt - T;
        red[tid] = d * d;
    }
    __syncthreads();
    if (tid == 0) {
        float a = 0.0f;
        for (int i = 0; i < 64; i++) a += red[i];
        g_tbpart[blk] = a;
    }
}

// ---------------- final reduction ----------------
__global__ void pinn_reduce(float* __restrict__ out) {
    __shared__ double sd[512];
    int tid = threadIdx.x;   // 512 threads

    double pv[4] = {0.0, 0.0, 0.0, 0.0};
    if (tid < N_SAMP/SPC) {
        pv[0] = (double)g_part[tid*4+0];
        pv[1] = (double)g_part[tid*4+1];
        pv[2] = (double)g_part[tid*4+2];
        pv[3] = (double)g_part[tid*4+3];
    }
    double tb = (tid < N_SAMP/SB) ? (double)g_tbpart[tid] : 0.0;

    double sums[5];
    double vals[5] = {pv[0], pv[1], pv[2], pv[3], tb};
    for (int q = 0; q < 5; q++) {
        sd[tid] = vals[q];
        __syncthreads();
        for (int o = 256; o > 0; o >>= 1) {
            if (tid < o) sd[tid] += sd[tid + o];
            __syncthreads();
        }
        sums[q] = sd[0];
        __syncthreads();
    }
    if (tid == 0) {
        double Nf = (double)N_SAMP;
        double total = sums[0]/(3.0*Nf)   // data
                     + sums[1]/Nf         // conti
                     + sums[2]/(3.0*Nf)   // NSE
                     + sums[3]/Nf         // EE
                     + sums[4]/Nf;        // Tb
        out[0] = (float)total;
    }
}

// ---------------- launch ----------------
extern "C" void kernel_launch(void* const* d_in, const int* in_sizes, int n_in,
                              void* d_out, int out_size) {
    const float* inputs = (const float*)d_in[0];
    const float* y_true = (const float*)d_in[1];
    const float* Win    = (const float*)d_in[2];
    const float* bin    = (const float*)d_in[3];
    const float* Wh     = (const float*)d_in[4];
    const float* bh     = (const float*)d_in[5];
    const float* Wo     = (const float*)d_in[6];
    const float* bo     = (const float*)d_in[7];
    float* out = (float*)d_out;

    size_t shm_main = (size_t)(ROWS*SSTR + D*D + 32 + 32) * sizeof(float);
    size_t shm_b    = (size_t)(SB*BSTR + D*D + 256) * sizeof(float);
    cudaFuncSetAttribute(pinn_main,  cudaFuncAttributeMaxDynamicSharedMemorySize, (int)shm_main);
    cudaFuncSetAttribute(pinn_bound, cudaFuncAttributeMaxDynamicSharedMemorySize, (int)shm_b);

    pinn_rng<<<16, 256>>>();
    pinn_main<<<N_SAMP/SPC, NTHR, shm_main>>>(inputs, y_true, Win, bin, Wh, bh, Wo, bo);
    pinn_bound<<<N_SAMP/SB, 256, shm_b>>>(inputs, Win, bin, Wh, bh, Wo, bo);
    pinn_reduce<<<1, 512>>>(out);
}

// round 4
// speedup vs baseline: 2.4296x; 2.4296x over previous
#include <cuda_runtime.h>
#include <cuda_bf16.h>
#include <cstdint>
#include <math.h>

#define N_SAMP 4096
#define D      128
#define NLAY   5
#define NCU    23
#define NCP    24

#define TWO_PI 6.2831853071795864769f
#define PI_F   3.1415926535897932385f
#define C2     19.739208802178717238f     /* 2*pi^2  */
#define C3     124.02510672119926149f     /* 4*pi^3  */
#define S_CONST 8.3666002653407556e-04f   /* sqrt(0.7/1e6) */
#define KAPPA   1.1952286093343936e-03f   /* sqrt(1/7e5)   */

#define NMAIN  512          // main CTAs: 8 samples (192 jet rows)
#define NBND   32           // boundary CTAs: 128 samples (128 value rows)

#define SROWB  272          // state/weight row stride in bytes (136 halves)

// ------- smem layout (bytes) -------
#define SM_BIN   0          // 128 f
#define SM_BO    512        // 4 f
#define SM_BH    528        // 640 f
#define SM_WIN   3088       // 512 f
#define SM_WO    5136       // 512 f
#define SM_X     7184       // up to 512 f
#define SM_YT    9232       // 32 f
#define SM_YC    9360       // 736 f (main) / 128 f red (boundary)
#define SM_LS    12304      // 32 f
#define SM_WHI   16384      // 34816 B
#define SM_WLO   51200      // 34816 B
#define SM_SHI   86016      // 192*272 = 52224 B
#define SM_SLO   138240     // 52224 B
#define SMEM_TOTAL 190464

// ------- global scratch -------
__device__ float g_xy[2*N_SAMP];
__device__ float g_zb[N_SAMP];
__device__ float g_part[NMAIN*4];
__device__ float g_tbpart[NBND];
__device__ __align__(16) __nv_bfloat16 g_WtH[NLAY*D*136];
__device__ __align__(16) __nv_bfloat16 g_WtL[NLAY*D*136];

// ------- PTX helpers (baseline sm_80-class only) -------
__device__ __forceinline__ uint32_t smem_u32(const void* p) {
    uint32_t a;
    asm("{ .reg .u64 t; cvta.to.shared.u64 t, %1; cvt.u32.u64 %0, t; }" : "=r"(a) : "l"(p));
    return a;
}
#define LDSM4(r, addr) \
    asm volatile("ldmatrix.sync.aligned.m8n8.x4.shared.b16 {%0,%1,%2,%3}, [%4];" \
        : "=r"((r)[0]),"=r"((r)[1]),"=r"((r)[2]),"=r"((r)[3]) : "r"(addr))
#define MMA16816(d, a, b0, b1) \
    asm volatile("mma.sync.aligned.m16n8k16.row.col.f32.bf16.bf16.f32 " \
        "{%0,%1,%2,%3}, {%4,%5,%6,%7}, {%8,%9}, {%0,%1,%2,%3};" \
        : "+f"((d)[0]),"+f"((d)[1]),"+f"((d)[2]),"+f"((d)[3]) \
        : "r"((a)[0]),"r"((a)[1]),"r"((a)[2]),"r"((a)[3]), "r"(b0),"r"(b1))
#define CPASYNC16(dst, src) \
    asm volatile("cp.async.cg.shared.global [%0], [%1], 16;" :: "r"(dst), "l"(src))
#define CPCOMMIT() asm volatile("cp.async.commit_group;" ::: "memory")
#define CPWAIT0()  asm volatile("cp.async.wait_group 0;" ::: "memory")

// ------- threefry2x32-20 (exact JAX) -------
__device__ __forceinline__ void tf2(uint32_t k0, uint32_t k1, uint32_t x0, uint32_t x1,
                                    uint32_t& o0, uint32_t& o1) {
    uint32_t ks2 = k0 ^ k1 ^ 0x1BD11BDAu;
    x0 += k0; x1 += k1;
#define TF_R(r) { x0 += x1; x1 = (x1 << (r)) | (x1 >> (32-(r))); x1 ^= x0; }
    TF_R(13) TF_R(15) TF_R(26) TF_R(6)
    x0 += k1;  x1 += ks2 + 1u;
    TF_R(17) TF_R(29) TF_R(16) TF_R(24)
    x0 += ks2; x1 += k0 + 2u;
    TF_R(13) TF_R(15) TF_R(26) TF_R(6)
    x0 += k0;  x1 += k1 + 3u;
    TF_R(17) TF_R(29) TF_R(16) TF_R(24)
    x0 += k1;  x1 += ks2 + 4u;
    TF_R(13) TF_R(15) TF_R(26) TF_R(6)
    x0 += ks2; x1 += k0 + 5u;
#undef TF_R
    o0 = x0; o1 = x1;
}
__device__ __forceinline__ float u01(uint32_t bits) {
    return __uint_as_float((bits >> 9) | 0x3F800000u) - 1.0f;
}

// ------- prep: weight transpose + bf16 hi/lo split + rng -------
__global__ void __launch_bounds__(256) pinn_prep(const float* __restrict__ Wh) {
    int b = blockIdx.x;
    if (b < 320) {
        int idx = b * 256 + threadIdx.x;        // 0..81919
        int l = idx >> 14;
        int rem = idx & 16383;
        int n = rem >> 7, k = rem & 127;        // Wt[n][k] = W[k][n]
        float v = Wh[l * 16384 + k * 128 + n];
        __nv_bfloat16 h = __float2bfloat16(v);
        __nv_bfloat16 lo = __float2bfloat16(v - __bfloat162float(h));
        g_WtH[(l * 128 + n) * 136 + k] = h;
        g_WtL[(l * 128 + n) * 136 + k] = lo;
    } else {
        int i = (b - 320) * 256 + threadIdx.x;  // 0..4095
        uint32_t a0, a1, b0, b1;
        tf2(0u, 22u, 0u, 2u, a0, a1);
        tf2(0u, 22u, 1u, 3u, b0, b1);
        uint32_t o0, o1;
        tf2(a0, b0, (uint32_t)i, (uint32_t)(i + 4096), o0, o1);
        g_xy[i]        = u01(o0);
        g_xy[i + 4096] = u01(o1);
        if (i < 2048) {
            uint32_t r0, r1;
            tf2(a1, b1, (uint32_t)i, (uint32_t)(i + 2048), r0, r1);
            g_zb[i]        = (float)(r0 & 1u);
            g_zb[i + 2048] = (float)(r1 & 1u);
        }
    }
}

// ------- activation jet propagation -------
__device__ __forceinline__ void act_prop(float z[NCU]) {
    const int p2a[9] = {0,0,0,1,1,1,2,2,3};
    const int p2b[9] = {1,2,3,1,2,3,2,3,3};
    const int t3a[9] = {1,2,3,1,2,3,1,2,3};
    const int t3b[9] = {1,1,1,2,2,2,3,3,3};
    const int s2s[4][4] = { {0,0,1,2}, {0,3,4,5}, {1,4,6,7}, {2,5,7,8} };

    float sv, cv;
    __sincosf(TWO_PI * z[0], &sv, &cv);
    float f0 = 0.5f * sv;
    float f1 = PI_F * cv;
    float f2 = -C2 * sv;
    float f3 = -C3 * cv;

    float d1[4], d2[9], d3[9];
#pragma unroll
    for (int i = 0; i < 4; i++) d1[i] = z[1+i];
#pragma unroll
    for (int p = 0; p < 9; p++) d2[p] = z[5+p];
#pragma unroll
    for (int q = 0; q < 9; q++) d3[q] = z[14+q];

    z[0] = f0;
#pragma unroll
    for (int i = 0; i < 4; i++) z[1+i] = f1 * d1[i];
#pragma unroll
    for (int p = 0; p < 9; p++)
        z[5+p] = f1 * d2[p] + f2 * d1[p2a[p]] * d1[p2b[p]];
#pragma unroll
    for (int q = 0; q < 9; q++) {
        int a = t3a[q], bq = t3b[q];
        float zbb = d2[s2s[bq][bq]];
        float zab = d2[s2s[a][bq]];
        z[14+q] = f1 * d3[q] + f2 * (d1[a]*zbb + 2.0f*d1[bq]*zab) + f3 * d1[a]*d1[bq]*d1[bq];
    }
}

// ------- bf16 hi/lo split helpers -------
__device__ __forceinline__ void split_pair(float x, float y, uint32_t& hi, uint32_t& lo) {
    __nv_bfloat16 xh = __float2bfloat16(x), yh = __float2bfloat16(y);
    __nv_bfloat16 xl = __float2bfloat16(x - __bfloat162float(xh));
    __nv_bfloat16 yl = __float2bfloat16(y - __bfloat162float(yh));
    hi = (uint32_t)__bfloat16_as_ushort(xh) | ((uint32_t)__bfloat16_as_ushort(yh) << 16);
    lo = (uint32_t)__bfloat16_as_ushort(xl) | ((uint32_t)__bfloat16_as_ushort(yl) << 16);
}
__device__ __forceinline__ void split_one(float x, char* sm, int r, int c) {
    __nv_bfloat16 xh = __float2bfloat16(x);
    __nv_bfloat16 xl = __float2bfloat16(x - __bfloat162float(xh));
    *(__nv_bfloat16*)(sm + SM_SHI + r*SROWB + c*2) = xh;
    *(__nv_bfloat16*)(sm + SM_SLO + r*SROWB + c*2) = xl;
}
__device__ __forceinline__ float ld_elem(const char* sm, int r, int c) {
    return __bfloat162float(*(const __nv_bfloat16*)(sm + SM_SHI + r*SROWB + c*2))
         + __bfloat162float(*(const __nv_bfloat16*)(sm + SM_SLO + r*SROWB + c*2));
}

// ------- 3-term bf16 GEMM via mma.sync (HMMA) -------
// out rows = MT*16 per warp starting at row0; cols = 64 starting at col0
template<int MT>
__device__ __forceinline__ void gemm3(uint32_t smb, int row0, int col0, int lane,
                                      float acc[MT][8][4]) {
#pragma unroll
    for (int i = 0; i < MT; i++)
#pragma unroll
        for (int j = 0; j < 8; j++)
#pragma unroll
            for (int q = 0; q < 4; q++) acc[i][j][q] = 0.0f;

    int rA = (lane & 7) + ((lane >> 3) & 1) * 8;
    int kA = (lane >> 4) * 8;
    int nB = (lane & 7) + ((lane >> 4) & 1) * 8;
    int kB = ((lane >> 3) & 1) * 8;

    uint32_t aH0 = smb + SM_SHI + (uint32_t)(row0 + rA) * SROWB + kA * 2;
    uint32_t aL0 = smb + SM_SLO + (uint32_t)(row0 + rA) * SROWB + kA * 2;
    uint32_t bH0 = smb + SM_WHI + (uint32_t)(col0 + nB) * SROWB + kB * 2;
    uint32_t bL0 = smb + SM_WLO + (uint32_t)(col0 + nB) * SROWB + kB * 2;

#pragma unroll
    for (int kc = 0; kc < 8; kc++) {
        uint32_t ko = kc * 32;   // 16 halves
        uint32_t aH[MT][4], aL[MT][4], bH[4][4], bL[4][4];
#pragma unroll
        for (int i = 0; i < MT; i++) {
            LDSM4(aH[i], aH0 + (uint32_t)(i * 16) * SROWB + ko);
            LDSM4(aL[i], aL0 + (uint32_t)(i * 16) * SROWB + ko);
        }
#pragma unroll
        for (int j = 0; j < 4; j++) {
            LDSM4(bH[j], bH0 + (uint32_t)(j * 16) * SROWB + ko);
            LDSM4(bL[j], bL0 + (uint32_t)(j * 16) * SROWB + ko);
        }
#pragma unroll
        for (int i = 0; i < MT; i++)
#pragma unroll
            for (int j2 = 0; j2 < 8; j2++) {
                const uint32_t* bh = &bH[j2 >> 1][(j2 & 1) * 2];
                const uint32_t* bl = &bL[j2 >> 1][(j2 & 1) * 2];
                MMA16816(acc[i][j2], aH[i], bh[0], bh[1]);
                MMA16816(acc[i][j2], aH[i], bl[0], bl[1]);
                MMA16816(acc[i][j2], aL[i], bh[0], bh[1]);
            }
    }
}

template<int MT>
__device__ __forceinline__ void store_acc(char* sm, int row0, int col0, int lane,
                                          float acc[MT][8][4]) {
    int g = lane >> 2, t = lane & 3;
#pragma unroll
    for (int i = 0; i < MT; i++)
#pragma unroll
        for (int j2 = 0; j2 < 8; j2++) {
            int r = row0 + i * 16 + g;
            int c = col0 + j2 * 8 + 2 * t;
            uint32_t hi, lo;
            split_pair(acc[i][j2][0], acc[i][j2][1], hi, lo);
            *(uint32_t*)(sm + SM_SHI + r * SROWB + c * 2) = hi;
            *(uint32_t*)(sm + SM_SLO + r * SROWB + c * 2) = lo;
            split_pair(acc[i][j2][2], acc[i][j2][3], hi, lo);
            *(uint32_t*)(sm + SM_SHI + (r + 8) * SROWB + c * 2) = hi;
            *(uint32_t*)(sm + SM_SLO + (r + 8) * SROWB + c * 2) = lo;
        }
}

__device__ __forceinline__ void stage_weights(char* sm, int tid, int l) {
    const char* srcH = (const char*)g_WtH + l * 34816;
    const char* srcL = (const char*)g_WtL + l * 34816;
    uint32_t dH = smem_u32(sm + SM_WHI);
    uint32_t dL = smem_u32(sm + SM_WLO);
    for (int i = tid * 16; i < 34816; i += 256 * 16) {
        CPASYNC16(dH + i, srcH + i);
        CPASYNC16(dL + i, srcL + i);
    }
    CPCOMMIT();
}

// ------- fused tensor-core kernel -------
__global__ void __launch_bounds__(256, 1)
pinn_tc(const float* __restrict__ inputs, const float* __restrict__ y_true,
        const float* __restrict__ Win, const float* __restrict__ bin,
        const float* __restrict__ bh,  const float* __restrict__ Wo,
        const float* __restrict__ bo)
{
    extern __shared__ char sm[];
    uint32_t smb = smem_u32(sm);
    int tid = threadIdx.x;
    int bid = blockIdx.x;
    bool is_b = (bid >= NMAIN);

    float* s_bin = (float*)(sm + SM_BIN);
    float* s_bo  = (float*)(sm + SM_BO);
    float* s_bh  = (float*)(sm + SM_BH);
    float* s_Win = (float*)(sm + SM_WIN);
    float* s_Wo  = (float*)(sm + SM_WO);
    float* s_x   = (float*)(sm + SM_X);
    float* s_yt  = (float*)(sm + SM_YT);
    float* s_yc  = (float*)(sm + SM_YC);
    float* s_red = (float*)(sm + SM_YC);
    float* s_ls  = (float*)(sm + SM_LS);

    // ---- prologue ----
    if (tid < 128) s_bin[tid] = bin[tid];
    for (int i = tid; i < 640; i += 256) s_bh[i] = bh[i];
    for (int i = tid; i < 512; i += 256) { s_Win[i] = Win[i]; s_Wo[i] = Wo[i]; }
    if (tid < 4) s_bo[tid] = bo[tid];
    if (!is_b) {
        if (tid < 32) { s_x[tid] = inputs[bid*32 + tid]; s_yt[tid] = y_true[bid*32 + tid]; }
    } else {
        int gs0 = (bid - NMAIN) * 128;
        if (tid < 128) {
            int gs = gs0 + tid;
            s_x[tid*4+0] = inputs[gs*4];
            s_x[tid*4+1] = g_xy[2*gs];
            s_x[tid*4+2] = g_xy[2*gs+1];
            s_x[tid*4+3] = g_zb[gs];
        }
    }
    stage_weights(sm, tid, 0);   // prefetch layer-0 weights
    __syncthreads();

    int lane = tid & 31;
    int w = tid >> 5;
    int wm = w >> 1, wn = w & 1;
    int col0 = wn * 64;
    int nn = tid & 127;          // neuron for elementwise phases
    int sg = tid >> 7;           // 0/1

    // ---- input layer ----
    if (!is_b) {
        float wn0 = s_Win[nn], wn1 = s_Win[128+nn], wn2 = s_Win[256+nn], wn3 = s_Win[384+nn];
        float bn = s_bin[nn];
#pragma unroll
        for (int jj = 0; jj < 4; jj++) {
            int s = sg * 4 + jj;
            float z[NCU];
            z[0] = bn + s_x[s*4]*wn0 + s_x[s*4+1]*wn1 + s_x[s*4+2]*wn2 + s_x[s*4+3]*wn3;
            z[1] = wn0; z[2] = wn1; z[3] = wn2; z[4] = wn3;
#pragma unroll
            for (int c = 5; c < NCU; c++) z[c] = 0.0f;
            act_prop(z);
            int rb = s * NCP;
#pragma unroll
            for (int c = 0; c < NCU; c++) split_one(z[c], sm, rb + c, nn);
            split_one(0.0f, sm, rb + 23, nn);
        }
    } else {
        float wn0 = s_Win[nn], wn1 = s_Win[128+nn], wn2 = s_Win[256+nn], wn3 = s_Win[384+nn];
        float bn = s_bin[nn];
        for (int s = sg * 64; s < sg * 64 + 64; s++) {
            float z = bn + s_x[s*4]*wn0 + s_x[s*4+1]*wn1 + s_x[s*4+2]*wn2 + s_x[s*4+3]*wn3;
            split_one(0.5f * __sinf(TWO_PI * z), sm, s, nn);
        }
    }

    // ---- hidden layers ----
    for (int l = 0; l < NLAY; l++) {
        CPWAIT0();
        __syncthreads();

        if (!is_b) {
            float acc[3][8][4];
            gemm3<3>(smb, wm * 48, col0, lane, acc);
            __syncthreads();
            if (l < NLAY-1) stage_weights(sm, tid, l + 1);
            store_acc<3>(sm, wm * 48, col0, lane, acc);
        } else {
            float acc[2][8][4];
            gemm3<2>(smb, wm * 32, col0, lane, acc);
            __syncthreads();
            if (l < NLAY-1) stage_weights(sm, tid, l + 1);
            store_acc<2>(sm, wm * 32, col0, lane, acc);
        }
        __syncthreads();

        // ---- activation ----
        float bn = s_bh[l*128 + nn];
        if (!is_b) {
#pragma unroll
            for (int jj = 0; jj < 4; jj++) {
                int s = sg * 4 + jj;
                int rb = s * NCP;
                float z[NCU];
#pragma unroll
                for (int c = 0; c < NCU; c++) z[c] = ld_elem(sm, rb + c, nn);
                z[0] += bn;
                act_prop(z);
#pragma unroll
                for (int c = 0; c < NCU; c++) split_one(z[c], sm, rb + c, nn);
            }
        } else {
            for (int s = sg * 64; s < sg * 64 + 64; s++) {
                float z = ld_elem(sm, s, nn) + bn;
                split_one(0.5f * __sinf(TWO_PI * z), sm, s, nn);
            }
        }
    }
    __syncthreads();

    // ---- output layer + losses ----
    if (!is_b) {
        if (tid < 192) {
            int s = tid / NCP, c = tid % NCP;
            if (c < NCU) {
                float a0 = 0, a1 = 0, a2 = 0, a3 = 0;
                for (int k = 0; k < D; k++) {
                    float h = ld_elem(sm, tid, k);
                    a0 += h * s_Wo[k*4+0];
                    a1 += h * s_Wo[k*4+1];
                    a2 += h * s_Wo[k*4+2];
                    a3 += h * s_Wo[k*4+3];
                }
                if (c == 0) { a0 += s_bo[0]; a1 += s_bo[1]; a2 += s_bo[2]; a3 += s_bo[3]; }
                s_yc[(s*NCU + c)*4 + 0] = a0;
                s_yc[(s*NCU + c)*4 + 1] = a1;
                s_yc[(s*NCU + c)*4 + 2] = a2;
                s_yc[(s*NCU + c)*4 + 3] = a3;
            }
        }
        __syncthreads();
        if (tid < 8) {
            const int s = tid;
            const int s2c[4][4] = { {0,5,6,7}, {5,8,9,10}, {6,9,11,12}, {7,10,12,13} };
            auto YC = [&](int c, int o) { return s_yc[(s*NCU + c)*4 + o]; };
            auto Hc = [&](int o, int i, int j) { return YC(s2c[i][j], o); };
            auto Gc = [&](int o, int a, int b2) { return YC(14 + (b2-1)*3 + (a-1), o); };
            auto J  = [&](int o, int i) { return YC(1+i, o); };

            float u = YC(0,0), v = YC(0,1), wv = YC(0,2);
            float u_x=J(0,1), u_y=J(0,2), u_z=J(0,3);
            float v_x=J(1,1), v_y=J(1,2), v_z=J(1,3);
            float w_x=J(2,1), w_y=J(2,2), w_z=J(2,3);
            float T_t=J(3,0), T_x=J(3,1), T_y=J(3,2), T_z=J(3,3);

            float om_x = w_y - v_z, om_y = u_z - w_x, om_z = v_x - u_y;

            float NSE_u = Hc(2,2,0) - Hc(1,3,0)
                        + u*(Hc(2,2,1)-Hc(1,3,1)) + v*(Hc(2,2,2)-Hc(1,3,2)) + wv*(Hc(2,2,3)-Hc(1,3,3))
                        - om_x*u_x - om_y*u_y - om_z*u_z
                        - S_CONST*( Gc(2,2,1)-Gc(1,3,1) + Gc(2,2,2)-Gc(1,3,2) + Gc(2,2,3)-Gc(1,3,3) )
                        - T_y;
            float NSE_v = Hc(0,3,0) - Hc(2,1,0)
                        + u*(Hc(0,3,1)-Hc(2,1,1)) + v*(Hc(0,3,2)-Hc(2,1,2)) + wv*(Hc(0,3,3)-Hc(2,1,3))
                        - om_x*v_x - om_y*v_y - om_z*v_z
                        - S_CONST*( Gc(0,3,1)-Gc(2,1,1) + Gc(0,3,2)-Gc(2,1,2) + Gc(0,3,3)-Gc(2,1,3) )
                        + T_x;
            float NSE_w = Hc(1,1,0) - Hc(0,2,0)
                        + u*(Hc(1,1,1)-Hc(0,2,1)) + v*(Hc(1,1,2)-Hc(0,2,2)) + wv*(Hc(1,1,3)-Hc(0,2,3))
                        - om_x*w_x - om_y*w_y - om_z*w_z
                        - S_CONST*( Gc(1,1,1)-Gc(0,2,1) + Gc(1,1,2)-Gc(0,2,2) + Gc(1,1,3)-Gc(0,2,3) );
            float EE = T_t + u*T_x + v*T_y + wv*T_z
                     - KAPPA*( Hc(3,1,1) + Hc(3,2,2) + Hc(3,3,3) );

            float ld = 0.0f;
#pragma unroll
            for (int o = 0; o < 3; o++) {
                float dd = YC(0,o) - s_yt[s*4 + o];
                ld += dd*dd;
            }
            float conti = u_x + v_y + w_z;
            s_ls[s*4+0] = ld;
            s_ls[s*4+1] = conti*conti;
            s_ls[s*4+2] = NSE_u*NSE_u + NSE_v*NSE_v + NSE_w*NSE_w;
            s_ls[s*4+3] = EE*EE;
        }
        __syncthreads();
        if (tid == 0) {
            float a0=0, a1=0, a2=0, a3=0;
            for (int s = 0; s < 8; s++) {
                a0 += s_ls[s*4+0]; a1 += s_ls[s*4+1];
                a2 += s_ls[s*4+2]; a3 += s_ls[s*4+3];
            }
            g_part[bid*4+0] = a0; g_part[bid*4+1] = a1;
            g_part[bid*4+2] = a2; g_part[bid*4+3] = a3;
        }
    } else {
        if (tid < 128) {
            float acc = 0.0f;
            for (int k = 0; k < D; k++)
                acc += ld_elem(sm, tid, k) * s_Wo[k*4+3];
            float T = acc + s_bo[3];
            float Tt = (s_x[tid*4+3] == 0.0f) ? 0.5f : -0.5f;
            float dd = Tt - T;
            s_red[tid] = dd * dd;
        }
        __syncthreads();
        if (tid == 0) {
            float a = 0.0f;
            for (int i = 0; i < 128; i++) a += s_red[i];
            g_tbpart[bid - NMAIN] = a;
        }
    }
}

// ------- final reduction -------
__global__ void __launch_bounds__(256) pinn_reduce(float* __restrict__ out) {
    __shared__ double sacc[8][5];
    int tid = threadIdx.x;
    double v[5] = {0, 0, 0, 0, 0};
    for (int i = tid; i < NMAIN; i += 256) {
        v[0] += (double)g_part[i*4+0];
        v[1] += (double)g_part[i*4+1];
        v[2] += (double)g_part[i*4+2];
        v[3] += (double)g_part[i*4+3];
    }
    if (tid < NBND) v[4] = (double)g_tbpart[tid];
#pragma unroll
    for (int o = 16; o; o >>= 1)
#pragma unroll
        for (int q = 0; q < 5; q++)
            v[q] += __shfl_down_sync(0xFFFFFFFFu, v[q], o);
    if ((tid & 31) == 0)
#pragma unroll
        for (int q = 0; q < 5; q++) sacc[tid >> 5][q] = v[q];
    __syncthreads();
    if (tid == 0) {
        double s[5] = {0, 0, 0, 0, 0};
        for (int ww = 0; ww < 8; ww++)
#pragma unroll
            for (int q = 0; q < 5; q++) s[q] += sacc[ww][q];
        double Nf = (double)N_SAMP;
        out[0] = (float)(s[0]/(3.0*Nf) + s[1]/Nf + s[2]/(3.0*Nf) + s[3]/Nf + s[4]/Nf);
    }
}

// ------- launch -------
extern "C" void kernel_launch(void* const* d_in, const int* in_sizes, int n_in,
                              void* d_out, int out_size) {
    const float* inputs = (const float*)d_in[0];
    const float* y_true = (const float*)d_in[1];
    const float* Win    = (const float*)d_in[2];
    const float* bin    = (const float*)d_in[3];
    const float* Wh     = (const float*)d_in[4];
    const float* bh     = (const float*)d_in[5];
    const float* Wo     = (const float*)d_in[6];
    const float* bo     = (const float*)d_in[7];
    float* out = (float*)d_out;

    cudaFuncSetAttribute(pinn_tc, cudaFuncAttributeMaxDynamicSharedMemorySize, SMEM_TOTAL);

    pinn_prep<<<336, 256>>>(Wh);
    pinn_tc<<<NMAIN + NBND, 256, SMEM_TOTAL>>>(inputs, y_true, Win, bin, bh, Wo, bo);
    pinn_reduce<<<1, 256>>>(out);
}

// round 5
// speedup vs baseline: 2.6780x; 1.1022x over previous
#include <cuda_runtime.h>
#include <cuda_bf16.h>
#include <cstdint>
#include <math.h>

#define N_SAMP 4096
#define D      128
#define NLAY   5
#define NCU    23
#define NCP    24

#define TWO_PI 6.2831853071795864769f
#define PI_F   3.1415926535897932385f
#define C2     19.739208802178717238f     /* 2*pi^2  */
#define C3     124.02510672119926149f     /* 4*pi^3  */
#define S_CONST 8.3666002653407556e-04f   /* sqrt(0.7/1e6) */
#define KAPPA   1.1952286093343936e-03f   /* sqrt(1/7e5)   */

#define NMAIN  512          // main CTAs: 8 samples (192 jet rows)
#define NBND   32           // boundary CTAs: 128 samples (128 value rows)

#define SROWB  272          // bf16 state/weight row stride (bytes)
#define FROWB  544          // fp32 accum row stride (bytes) = 136 floats

// ------- smem layout (bytes) -------
#define SM_BIN   0          // 128 f
#define SM_BO    512        // 4 f
#define SM_BH    528        // 640 f
#define SM_WIN   3088       // 512 f
#define SM_WO    5136       // 512 f
#define SM_X     7184       // up to 512 f
#define SM_YT    9232       // 32 f
#define SM_YC    9360       // 736 f (main) / 128 f red (boundary)
#define SM_LS    12304      // 32 f
#define SM_WHI   16384      // 34816 B
#define SM_WLO   51200      // 34816 B
#define SM_SHI   86016      // bf16 hi tile: 192*272 = 52224 B
#define SM_SLO   138240     // bf16 lo tile: 52224 B
#define SM_F32   86016      // fp32 accum overlays both bf16 tiles: 192*544 = 104448 B
#define SMEM_TOTAL 190464

// ------- global scratch -------
__device__ float g_xy[2*N_SAMP];
__device__ float g_zb[N_SAMP];
__device__ float g_part[NMAIN*4];
__device__ float g_tbpart[NBND];
__device__ __align__(16) __nv_bfloat16 g_WtH[NLAY*D*136];
__device__ __align__(16) __nv_bfloat16 g_WtL[NLAY*D*136];

// ------- PTX helpers (baseline sm_80-class only) -------
__device__ __forceinline__ uint32_t smem_u32(const void* p) {
    uint32_t a;
    asm("{ .reg .u64 t; cvta.to.shared.u64 t, %1; cvt.u32.u64 %0, t; }" : "=r"(a) : "l"(p));
    return a;
}
#define LDSM4(r, addr) \
    asm volatile("ldmatrix.sync.aligned.m8n8.x4.shared.b16 {%0,%1,%2,%3}, [%4];" \
        : "=r"((r)[0]),"=r"((r)[1]),"=r"((r)[2]),"=r"((r)[3]) : "r"(addr))
#define MMA16816(d, a, b0, b1) \
    asm volatile("mma.sync.aligned.m16n8k16.row.col.f32.bf16.bf16.f32 " \
        "{%0,%1,%2,%3}, {%4,%5,%6,%7}, {%8,%9}, {%0,%1,%2,%3};" \
        : "+f"((d)[0]),"+f"((d)[1]),"+f"((d)[2]),"+f"((d)[3]) \
        : "r"((a)[0]),"r"((a)[1]),"r"((a)[2]),"r"((a)[3]), "r"(b0),"r"(b1))
#define CPASYNC16(dst, src) \
    asm volatile("cp.async.cg.shared.global [%0], [%1], 16;" :: "r"(dst), "l"(src))
#define CPCOMMIT() asm volatile("cp.async.commit_group;" ::: "memory")
#define CPWAIT0()  asm volatile("cp.async.wait_group 0;" ::: "memory")

// ------- threefry2x32-20 (exact JAX) -------
__device__ __forceinline__ void tf2(uint32_t k0, uint32_t k1, uint32_t x0, uint32_t x1,
                                    uint32_t& o0, uint32_t& o1) {
    uint32_t ks2 = k0 ^ k1 ^ 0x1BD11BDAu;
    x0 += k0; x1 += k1;
#define TF_R(r) { x0 += x1; x1 = (x1 << (r)) | (x1 >> (32-(r))); x1 ^= x0; }
    TF_R(13) TF_R(15) TF_R(26) TF_R(6)
    x0 += k1;  x1 += ks2 + 1u;
    TF_R(17) TF_R(29) TF_R(16) TF_R(24)
    x0 += ks2; x1 += k0 + 2u;
    TF_R(13) TF_R(15) TF_R(26) TF_R(6)
    x0 += k0;  x1 += k1 + 3u;
    TF_R(17) TF_R(29) TF_R(16) TF_R(24)
    x0 += k1;  x1 += ks2 + 4u;
    TF_R(13) TF_R(15) TF_R(26) TF_R(6)
    x0 += ks2; x1 += k0 + 5u;
#undef TF_R
    o0 = x0; o1 = x1;
}
__device__ __forceinline__ float u01(uint32_t bits) {
    return __uint_as_float((bits >> 9) | 0x3F800000u) - 1.0f;
}

// ------- prep: weight transpose + bf16 hi/lo split + rng -------
__global__ void __launch_bounds__(256) pinn_prep(const float* __restrict__ Wh) {
    int b = blockIdx.x;
    if (b < 320) {
        int idx = b * 256 + threadIdx.x;        // 0..81919
        int l = idx >> 14;
        int rem = idx & 16383;
        int n = rem >> 7, k = rem & 127;        // Wt[n][k] = W[k][n]
        float v = Wh[l * 16384 + k * 128 + n];
        __nv_bfloat16 h = __float2bfloat16(v);
        __nv_bfloat16 lo = __float2bfloat16(v - __bfloat162float(h));
        g_WtH[(l * 128 + n) * 136 + k] = h;
        g_WtL[(l * 128 + n) * 136 + k] = lo;
    } else {
        int i = (b - 320) * 256 + threadIdx.x;  // 0..4095
        uint32_t a0, a1, b0, b1;
        tf2(0u, 22u, 0u, 2u, a0, a1);
        tf2(0u, 22u, 1u, 3u, b0, b1);
        uint32_t o0, o1;
        tf2(a0, b0, (uint32_t)i, (uint32_t)(i + 4096), o0, o1);
        g_xy[i]        = u01(o0);
        g_xy[i + 4096] = u01(o1);
        if (i < 2048) {
            uint32_t r0, r1;
            tf2(a1, b1, (uint32_t)i, (uint32_t)(i + 2048), r0, r1);
            g_zb[i]        = (float)(r0 & 1u);
            g_zb[i + 2048] = (float)(r1 & 1u);
        }
    }
}

// ------- activation jet propagation -------
__device__ __forceinline__ void act_prop(float z[NCU]) {
    const int p2a[9] = {0,0,0,1,1,1,2,2,3};
    const int p2b[9] = {1,2,3,1,2,3,2,3,3};
    const int t3a[9] = {1,2,3,1,2,3,1,2,3};
    const int t3b[9] = {1,1,1,2,2,2,3,3,3};
    const int s2s[4][4] = { {0,0,1,2}, {0,3,4,5}, {1,4,6,7}, {2,5,7,8} };

    float sv, cv;
    __sincosf(TWO_PI * z[0], &sv, &cv);
    float f0 = 0.5f * sv;
    float f1 = PI_F * cv;
    float f2 = -C2 * sv;
    float f3 = -C3 * cv;

    float d1[4], d2[9], d3[9];
#pragma unroll
    for (int i = 0; i < 4; i++) d1[i] = z[1+i];
#pragma unroll
    for (int p = 0; p < 9; p++) d2[p] = z[5+p];
#pragma unroll
    for (int q = 0; q < 9; q++) d3[q] = z[14+q];

    z[0] = f0;
#pragma unroll
    for (int i = 0; i < 4; i++) z[1+i] = f1 * d1[i];
#pragma unroll
    for (int p = 0; p < 9; p++)
        z[5+p] = f1 * d2[p] + f2 * d1[p2a[p]] * d1[p2b[p]];
#pragma unroll
    for (int q = 0; q < 9; q++) {
        int a = t3a[q], bq = t3b[q];
        float zbb = d2[s2s[bq][bq]];
        float zab = d2[s2s[a][bq]];
        z[14+q] = f1 * d3[q] + f2 * (d1[a]*zbb + 2.0f*d1[bq]*zab) + f3 * d1[a]*d1[bq]*d1[bq];
    }
}

// ------- packed bf16 write of 4 lane-adjacent values -------
__device__ __forceinline__ void write_bf4(char* sm, int r, int c4, const float v[4]) {
    __nv_bfloat16 h0 = __float2bfloat16(v[0]);
    __nv_bfloat16 h1 = __float2bfloat16(v[1]);
    __nv_bfloat16 h2 = __float2bfloat16(v[2]);
    __nv_bfloat16 h3 = __float2bfloat16(v[3]);
    uint2 hi, lo;
    hi.x = (uint32_t)__bfloat16_as_ushort(h0) | ((uint32_t)__bfloat16_as_ushort(h1) << 16);
    hi.y = (uint32_t)__bfloat16_as_ushort(h2) | ((uint32_t)__bfloat16_as_ushort(h3) << 16);
    __nv_bfloat16 l0 = __float2bfloat16(v[0] - __bfloat162float(h0));
    __nv_bfloat16 l1 = __float2bfloat16(v[1] - __bfloat162float(h1));
    __nv_bfloat16 l2 = __float2bfloat16(v[2] - __bfloat162float(h2));
    __nv_bfloat16 l3 = __float2bfloat16(v[3] - __bfloat162float(h3));
    lo.x = (uint32_t)__bfloat16_as_ushort(l0) | ((uint32_t)__bfloat16_as_ushort(l1) << 16);
    lo.y = (uint32_t)__bfloat16_as_ushort(l2) | ((uint32_t)__bfloat16_as_ushort(l3) << 16);
    *(uint2*)(sm + SM_SHI + r * SROWB + c4 * 2) = hi;
    *(uint2*)(sm + SM_SLO + r * SROWB + c4 * 2) = lo;
}

// ------- 3-term bf16 GEMM via mma.sync (HMMA) -------
template<int MT>
__device__ __forceinline__ void gemm3(uint32_t smb, int row0, int col0, int lane,
                                      float acc[MT][8][4]) {
#pragma unroll
    for (int i = 0; i < MT; i++)
#pragma unroll
        for (int j = 0; j < 8; j++)
#pragma unroll
            for (int q = 0; q < 4; q++) acc[i][j][q] = 0.0f;

    int rA = (lane & 7) + ((lane >> 3) & 1) * 8;
    int kA = (lane >> 4) * 8;
    int nB = (lane & 7) + ((lane >> 4) & 1) * 8;
    int kB = ((lane >> 3) & 1) * 8;

    uint32_t aH0 = smb + SM_SHI + (uint32_t)(row0 + rA) * SROWB + kA * 2;
    uint32_t aL0 = smb + SM_SLO + (uint32_t)(row0 + rA) * SROWB + kA * 2;
    uint32_t bH0 = smb + SM_WHI + (uint32_t)(col0 + nB) * SROWB + kB * 2;
    uint32_t bL0 = smb + SM_WLO + (uint32_t)(col0 + nB) * SROWB + kB * 2;

#pragma unroll
    for (int kc = 0; kc < 8; kc++) {
        uint32_t ko = kc * 32;
        uint32_t aH[MT][4], aL[MT][4], bH[4][4], bL[4][4];
#pragma unroll
        for (int i = 0; i < MT; i++) {
            LDSM4(aH[i], aH0 + (uint32_t)(i * 16) * SROWB + ko);
            LDSM4(aL[i], aL0 + (uint32_t)(i * 16) * SROWB + ko);
        }
#pragma unroll
        for (int j = 0; j < 4; j++) {
            LDSM4(bH[j], bH0 + (uint32_t)(j * 16) * SROWB + ko);
            LDSM4(bL[j], bL0 + (uint32_t)(j * 16) * SROWB + ko);
        }
#pragma unroll
        for (int i = 0; i < MT; i++)
#pragma unroll
            for (int j2 = 0; j2 < 8; j2++) {
                const uint32_t* bh = &bH[j2 >> 1][(j2 & 1) * 2];
                const uint32_t* bl = &bL[j2 >> 1][(j2 & 1) * 2];
                MMA16816(acc[i][j2], aH[i], bh[0], bh[1]);
                MMA16816(acc[i][j2], aH[i], bl[0], bl[1]);
                MMA16816(acc[i][j2], aL[i], bh[0], bh[1]);
            }
    }
}

// store accumulators as fp32 into overlay region
template<int MT>
__device__ __forceinline__ void store_accf(char* sm, int row0, int col0, int lane,
                                           float acc[MT][8][4]) {
    int g = lane >> 2, t = lane & 3;
#pragma unroll
    for (int i = 0; i < MT; i++)
#pragma unroll
        for (int j2 = 0; j2 < 8; j2++) {
            int r = row0 + i * 16 + g;
            int c = col0 + j2 * 8 + 2 * t;
            *(float2*)(sm + SM_F32 + r * FROWB + c * 4) = make_float2(acc[i][j2][0], acc[i][j2][1]);
            *(float2*)(sm + SM_F32 + (r + 8) * FROWB + c * 4) = make_float2(acc[i][j2][2], acc[i][j2][3]);
        }
}

__device__ __forceinline__ void stage_weights(char* sm, int tid, int l) {
    const char* srcH = (const char*)g_WtH + l * 34816;
    const char* srcL = (const char*)g_WtL + l * 34816;
    uint32_t dH = smem_u32(sm + SM_WHI);
    uint32_t dL = smem_u32(sm + SM_WLO);
    for (int i = tid * 16; i < 34816; i += 256 * 16) {
        CPASYNC16(dH + i, srcH + i);
        CPASYNC16(dL + i, srcL + i);
    }
    CPCOMMIT();
}

// ------- fused tensor-core kernel -------
__global__ void __launch_bounds__(256, 1)
pinn_tc(const float* __restrict__ inputs, const float* __restrict__ y_true,
        const float* __restrict__ Win, const float* __restrict__ bin,
        const float* __restrict__ bh,  const float* __restrict__ Wo,
        const float* __restrict__ bo)
{
    extern __shared__ char sm[];
    uint32_t smb = smem_u32(sm);
    int tid = threadIdx.x;
    int bid = blockIdx.x;
    bool is_b = (bid >= NMAIN);

    float* s_bin = (float*)(sm + SM_BIN);
    float* s_bo  = (float*)(sm + SM_BO);
    float* s_bh  = (float*)(sm + SM_BH);
    float* s_Win = (float*)(sm + SM_WIN);
    float* s_Wo  = (float*)(sm + SM_WO);
    float* s_x   = (float*)(sm + SM_X);
    float* s_yt  = (float*)(sm + SM_YT);
    float* s_yc  = (float*)(sm + SM_YC);
    float* s_red = (float*)(sm + SM_YC);
    float* s_ls  = (float*)(sm + SM_LS);

    // ---- prologue ----
    if (tid < 128) s_bin[tid] = bin[tid];
    for (int i = tid; i < 640; i += 256) s_bh[i] = bh[i];
    for (int i = tid; i < 512; i += 256) { s_Win[i] = Win[i]; s_Wo[i] = Wo[i]; }
    if (tid < 4) s_bo[tid] = bo[tid];
    if (!is_b) {
        if (tid < 32) { s_x[tid] = inputs[bid*32 + tid]; s_yt[tid] = y_true[bid*32 + tid]; }
    } else {
        int gs0 = (bid - NMAIN) * 128;
        if (tid < 128) {
            int gs = gs0 + tid;
            s_x[tid*4+0] = inputs[gs*4];
            s_x[tid*4+1] = g_xy[2*gs];
            s_x[tid*4+2] = g_xy[2*gs+1];
            s_x[tid*4+3] = g_zb[gs];
        }
    }
    stage_weights(sm, tid, 0);
    __syncthreads();

    int lane = tid & 31;
    int w = tid >> 5;
    int wm = w >> 1, wn = w & 1;
    int col0 = wn * 64;
    int c4 = lane * 4;    // 4-neuron group for elementwise phases

    // ---- input layer ----
    if (!is_b) {
        int s = w;                       // warp <-> sample
        float zc[NCU][4];
#pragma unroll
        for (int n = 0; n < 4; n++) {
            int nn = c4 + n;
            float z[NCU];
            z[0] = s_bin[nn] + s_x[s*4]*s_Win[nn] + s_x[s*4+1]*s_Win[128+nn]
                 + s_x[s*4+2]*s_Win[256+nn] + s_x[s*4+3]*s_Win[384+nn];
            z[1] = s_Win[nn]; z[2] = s_Win[128+nn]; z[3] = s_Win[256+nn]; z[4] = s_Win[384+nn];
#pragma unroll
            for (int c = 5; c < NCU; c++) z[c] = 0.0f;
            act_prop(z);
#pragma unroll
            for (int c = 0; c < NCU; c++) zc[c][n] = z[c];
        }
#pragma unroll
        for (int c = 0; c < NCU; c++) write_bf4(sm, s*NCP + c, c4, zc[c]);
        float zz[4] = {0,0,0,0};
        write_bf4(sm, s*NCP + 23, c4, zz);
    } else {
        float wv0 = s_Win[c4], wv1 = s_Win[c4+1], wv2 = s_Win[c4+2], wv3 = s_Win[c4+3];
        float w10 = s_Win[128+c4], w11 = s_Win[128+c4+1], w12 = s_Win[128+c4+2], w13 = s_Win[128+c4+3];
        float w20 = s_Win[256+c4], w21 = s_Win[256+c4+1], w22 = s_Win[256+c4+2], w23 = s_Win[256+c4+3];
        float w30 = s_Win[384+c4], w31 = s_Win[384+c4+1], w32 = s_Win[384+c4+2], w33 = s_Win[384+c4+3];
        float b0 = s_bin[c4], b1 = s_bin[c4+1], b2 = s_bin[c4+2], b3 = s_bin[c4+3];
#pragma unroll
        for (int i = 0; i < 16; i++) {
            int s = w * 16 + i;
            float x0 = s_x[s*4], x1 = s_x[s*4+1], x2 = s_x[s*4+2], x3 = s_x[s*4+3];
            float v[4];
            v[0] = 0.5f * __sinf(TWO_PI * (b0 + x0*wv0 + x1*w10 + x2*w20 + x3*w30));
            v[1] = 0.5f * __sinf(TWO_PI * (b1 + x0*wv1 + x1*w11 + x2*w21 + x3*w31));
            v[2] = 0.5f * __sinf(TWO_PI * (b2 + x0*wv2 + x1*w12 + x2*w22 + x3*w32));
            v[3] = 0.5f * __sinf(TWO_PI * (b3 + x0*wv3 + x1*w13 + x2*w23 + x3*w33));
            write_bf4(sm, s, c4, v);
        }
    }

    // ---- hidden layers ----
    for (int l = 0; l < NLAY; l++) {
        CPWAIT0();
        __syncthreads();

        if (!is_b) {
            float acc[3][8][4];
            gemm3<3>(smb, wm * 48, col0, lane, acc);
            __syncthreads();
            if (l < NLAY-1) stage_weights(sm, tid, l + 1);
            store_accf<3>(sm, wm * 48, col0, lane, acc);
        } else {
            float acc[2][8][4];
            gemm3<2>(smb, wm * 32, col0, lane, acc);
            __syncthreads();
            if (l < NLAY-1) stage_weights(sm, tid, l + 1);
            store_accf<2>(sm, wm * 32, col0, lane, acc);
        }
        __syncthreads();

        // ---- activation (vectorized over 4 neurons) ----
        if (!is_b) {
            int s = w;
            float zc[NCU][4];
#pragma unroll
            for (int c = 0; c < NCU; c++) {
                float4 t4 = *(const float4*)(sm + SM_F32 + (s*NCP + c) * FROWB + c4 * 4);
                zc[c][0] = t4.x; zc[c][1] = t4.y; zc[c][2] = t4.z; zc[c][3] = t4.w;
            }
#pragma unroll
            for (int n = 0; n < 4; n++) {
                float z[NCU];
#pragma unroll
                for (int c = 0; c < NCU; c++) z[c] = zc[c][n];
                z[0] += s_bh[l*128 + c4 + n];
                act_prop(z);
#pragma unroll
                for (int c = 0; c < NCU; c++) zc[c][n] = z[c];
            }
            if (l == NLAY-1) {
                // write fp32 in place (thread-private) for output layer
#pragma unroll
                for (int c = 0; c < NCU; c++)
                    *(float4*)(sm + SM_F32 + (s*NCP + c) * FROWB + c4 * 4)
                        = make_float4(zc[c][0], zc[c][1], zc[c][2], zc[c][3]);
            } else {
                __syncthreads();   // all fp32 reads done before bf16 overwrite
#pragma unroll
                for (int c = 0; c < NCU; c++) write_bf4(sm, s*NCP + c, c4, zc[c]);
                float zz[4] = {0,0,0,0};
                write_bf4(sm, s*NCP + 23, c4, zz);
            }
        } else {
            float zc[16][4];
#pragma unroll
            for (int i = 0; i < 16; i++) {
                float4 t4 = *(const float4*)(sm + SM_F32 + (w*16 + i) * FROWB + c4 * 4);
                zc[i][0] = t4.x; zc[i][1] = t4.y; zc[i][2] = t4.z; zc[i][3] = t4.w;
            }
            float b0 = s_bh[l*128+c4], b1 = s_bh[l*128+c4+1], b2 = s_bh[l*128+c4+2], b3 = s_bh[l*128+c4+3];
#pragma unroll
            for (int i = 0; i < 16; i++) {
                zc[i][0] = 0.5f * __sinf(TWO_PI * (zc[i][0] + b0));
                zc[i][1] = 0.5f * __sinf(TWO_PI * (zc[i][1] + b1));
                zc[i][2] = 0.5f * __sinf(TWO_PI * (zc[i][2] + b2));
                zc[i][3] = 0.5f * __sinf(TWO_PI * (zc[i][3] + b3));
            }
            if (l == NLAY-1) {
#pragma unroll
                for (int i = 0; i < 16; i++)
                    *(float4*)(sm + SM_F32 + (w*16 + i) * FROWB + c4 * 4)
                        = make_float4(zc[i][0], zc[i][1], zc[i][2], zc[i][3]);
            } else {
                __syncthreads();
#pragma unroll
                for (int i = 0; i < 16; i++) write_bf4(sm, w*16 + i, c4, zc[i]);
            }
        }
    }
    __syncthreads();

    // ---- output layer + losses ----
    if (!is_b) {
        if (tid < 192) {
            int s = tid / NCP, c = tid % NCP;
            if (c < NCU) {
                float a0 = 0, a1 = 0, a2 = 0, a3 = 0;
                const float* hr = (const float*)(sm + SM_F32 + tid * FROWB);
                for (int k = 0; k < D; k++) {
                    float h = hr[k];
                    a0 += h * s_Wo[k*4+0];
                    a1 += h * s_Wo[k*4+1];
                    a2 += h * s_Wo[k*4+2];
                    a3 += h * s_Wo[k*4+3];
                }
                if (c == 0) { a0 += s_bo[0]; a1 += s_bo[1]; a2 += s_bo[2]; a3 += s_bo[3]; }
                s_yc[(s*NCU + c)*4 + 0] = a0;
                s_yc[(s*NCU + c)*4 + 1] = a1;
                s_yc[(s*NCU + c)*4 + 2] = a2;
                s_yc[(s*NCU + c)*4 + 3] = a3;
            }
        }
        __syncthreads();
        if (tid < 8) {
            const int s = tid;
            const int s2c[4][4] = { {0,5,6,7}, {5,8,9,10}, {6,9,11,12}, {7,10,12,13} };
            auto YC = [&](int c, int o) { return s_yc[(s*NCU + c)*4 + o]; };
            auto Hc = [&](int o, int i, int j) { return YC(s2c[i][j], o); };
            auto Gc = [&](int o, int a, int b2) { return YC(14 + (b2-1)*3 + (a-1), o); };
            auto J  = [&](int o, int i) { return YC(1+i, o); };

            float u = YC(0,0), v = YC(0,1), wv = YC(0,2);
            float u_x=J(0,1), u_y=J(0,2), u_z=J(0,3);
            float v_x=J(1,1), v_y=J(1,2), v_z=J(1,3);
            float w_x=J(2,1), w_y=J(2,2), w_z=J(2,3);
            float T_t=J(3,0), T_x=J(3,1), T_y=J(3,2), T_z=J(3,3);

            float om_x = w_y - v_z, om_y = u_z - w_x, om_z = v_x - u_y;

            float NSE_u = Hc(2,2,0) - Hc(1,3,0)
                        + u*(Hc(2,2,1)-Hc(1,3,1)) + v*(Hc(2,2,2)-Hc(1,3,2)) + wv*(Hc(2,2,3)-Hc(1,3,3))
                        - om_x*u_x - om_y*u_y - om_z*u_z
                        - S_CONST*( Gc(2,2,1)-Gc(1,3,1) + Gc(2,2,2)-Gc(1,3,2) + Gc(2,2,3)-Gc(1,3,3) )
                        - T_y;
            float NSE_v = Hc(0,3,0) - Hc(2,1,0)
                        + u*(Hc(0,3,1)-Hc(2,1,1)) + v*(Hc(0,3,2)-Hc(2,1,2)) + wv*(Hc(0,3,3)-Hc(2,1,3))
                        - om_x*v_x - om_y*v_y - om_z*v_z
                        - S_CONST*( Gc(0,3,1)-Gc(2,1,1) + Gc(0,3,2)-Gc(2,1,2) + Gc(0,3,3)-Gc(2,1,3) )
                        + T_x;
            float NSE_w = Hc(1,1,0) - Hc(0,2,0)
                        + u*(Hc(1,1,1)-Hc(0,2,1)) + v*(Hc(1,1,2)-Hc(0,2,2)) + wv*(Hc(1,1,3)-Hc(0,2,3))
                        - om_x*w_x - om_y*w_y - om_z*w_z
                        - S_CONST*( Gc(1,1,1)-Gc(0,2,1) + Gc(1,1,2)-Gc(0,2,2) + Gc(1,1,3)-Gc(0,2,3) );
            float EE = T_t + u*T_x + v*T_y + wv*T_z
                     - KAPPA*( Hc(3,1,1) + Hc(3,2,2) + Hc(3,3,3) );

            float ld = 0.0f;
#pragma unroll
            for (int o = 0; o < 3; o++) {
                float dd = YC(0,o) - s_yt[s*4 + o];
                ld += dd*dd;
            }
            float conti = u_x + v_y + w_z;
            s_ls[s*4+0] = ld;
            s_ls[s*4+1] = conti*conti;
            s_ls[s*4+2] = NSE_u*NSE_u + NSE_v*NSE_v + NSE_w*NSE_w;
            s_ls[s*4+3] = EE*EE;
        }
        __syncthreads();
        if (tid == 0) {
            float a0=0, a1=0, a2=0, a3=0;
            for (int s = 0; s < 8; s++) {
                a0 += s_ls[s*4+0]; a1 += s_ls[s*4+1];
                a2 += s_ls[s*4+2]; a3 += s_ls[s*4+3];
            }
            g_part[bid*4+0] = a0; g_part[bid*4+1] = a1;
            g_part[bid*4+2] = a2; g_part[bid*4+3] = a3;
        }
    } else {
        if (tid < 128) {
            float acc = 0.0f;
            const float* hr = (const float*)(sm + SM_F32 + tid * FROWB);
            for (int k = 0; k < D; k++)
                acc += hr[k] * s_Wo[k*4+3];
            float T = acc + s_bo[3];
            float Tt = (s_x[tid*4+3] == 0.0f) ? 0.5f : -0.5f;
            float dd = Tt - T;
            s_red[tid] = dd * dd;
        }
        __syncthreads();
        if (tid == 0) {
            float a = 0.0f;
            for (int i = 0; i < 128; i++) a += s_red[i];
            g_tbpart[bid - NMAIN] = a;
        }
    }
}

// ------- final reduction -------
__global__ void __launch_bounds__(256) pinn_reduce(float* __restrict__ out) {
    __shared__ double sacc[8][5];
    int tid = threadIdx.x;
    double v[5] = {0, 0, 0, 0, 0};
    for (int i = tid; i < NMAIN; i += 256) {
        v[0] += (double)g_part[i*4+0];
        v[1] += (double)g_part[i*4+1];
        v[2] += (double)g_part[i*4+2];
        v[3] += (double)g_part[i*4+3];
    }
    if (tid < NBND) v[4] = (double)g_tbpart[tid];
#pragma unroll
    for (int o = 16; o; o >>= 1)
#pragma unroll
        for (int q = 0; q < 5; q++)
            v[q] += __shfl_down_sync(0xFFFFFFFFu, v[q], o);
    if ((tid & 31) == 0)
#pragma unroll
        for (int q = 0; q < 5; q++) sacc[tid >> 5][q] = v[q];
    __syncthreads();
    if (tid == 0) {
        double s[5] = {0, 0, 0, 0, 0};
        for (int ww = 0; ww < 8; ww++)
#pragma unroll
            for (int q = 0; q < 5; q++) s[q] += sacc[ww][q];
        double Nf = (double)N_SAMP;
        out[0] = (float)(s[0]/(3.0*Nf) + s[1]/Nf + s[2]/(3.0*Nf) + s[3]/Nf + s[4]/Nf);
    }
}

// ------- launch -------
extern "C" void kernel_launch(void* const* d_in, const int* in_sizes, int n_in,
                              void* d_out, int out_size) {
    const float* inputs = (const float*)d_in[0];
    const float* y_true = (const float*)d_in[1];
    const float* Win    = (const float*)d_in[2];
    const float* bin    = (const float*)d_in[3];
    const float* Wh     = (const float*)d_in[4];
    const float* bh     = (const float*)d_in[5];
    const float* Wo     = (const float*)d_in[6];
    const float* bo     = (const float*)d_in[7];
    float* out = (float*)d_out;

    cudaFuncSetAttribute(pinn_tc, cudaFuncAttributeMaxDynamicSharedMemorySize, SMEM_TOTAL);

    pinn_prep<<<336, 256>>>(Wh);
    pinn_tc<<<NMAIN + NBND, 256, SMEM_TOTAL>>>(inputs, y_true, Win, bin, bh, Wo, bo);
    pinn_reduce<<<1, 256>>>(out);
}

// round 6
// speedup vs baseline: 3.2564x; 1.2160x over previous
#include <cuda_runtime.h>
#include <cuda_fp16.h>
#include <cstdint>
#include <math.h>

#define N_SAMP 4096
#define D      128
#define NLAY   5
#define NCU    23
#define NCP    24

#define TWO_PI 6.2831853071795864769f
#define PI_F   3.1415926535897932385f
#define C2     19.739208802178717238f     /* 2*pi^2  */
#define C3     124.02510672119926149f     /* 4*pi^3  */
#define S_CONST 8.3666002653407556e-04f   /* sqrt(0.7/1e6) */
#define KAPPA   1.1952286093343936e-03f   /* sqrt(1/7e5)   */

#define NMAIN  512          // main CTAs: 8 samples (192 jet rows)
#define NBND   32           // boundary CTAs: 128 samples (128 value rows)

#define SROWB  272          // fp16 state/weight row stride (bytes)
#define FROWB  544          // fp32 accum row stride (bytes) = 136 floats

// ------- smem layout (bytes) -------
#define SM_BIN   0          // 128 f
#define SM_BO    512        // 4 f
#define SM_BH    528        // 640 f
#define SM_WIN   3088       // 512 f
#define SM_WO    5136       // 512 f
#define SM_X     7184       // up to 512 f
#define SM_YT    9232       // 32 f
#define SM_YC    9360       // 736 f (main) / 128 f red (boundary)
#define SM_LS    12304      // 32 f
#define SM_W     16384      // fp16 weights: 128*272 = 34816 B
#define SM_SHI   51200      // fp16 state hi tile: 192*272 = 52224 B
#define SM_SLO   103424     // fp16 state lo tile: 52224 B
#define SM_F32   51200      // fp32 accum overlays both state tiles: 192*544 = 104448 B
#define SMEM_TOTAL 155648

// jet row scales (powers of 2; keep fp16 in range; exact)
#define SC1  0.0625f            /* 2^-4  */
#define SC2  0.00390625f        /* 2^-8  */
#define SC3  2.44140625e-4f     /* 2^-12 */
#define IS1  16.0f
#define IS2  256.0f
#define IS3  4096.0f

// ------- global scratch -------
__device__ float g_xy[2*N_SAMP];
__device__ float g_zb[N_SAMP];
__device__ float g_part[NMAIN*4];
__device__ float g_tbpart[NBND];
__device__ __align__(16) __half g_Wt[NLAY*D*136];

// ------- PTX helpers (baseline sm_80-class only) -------
__device__ __forceinline__ uint32_t smem_u32(const void* p) {
    uint32_t a;
    asm("{ .reg .u64 t; cvta.to.shared.u64 t, %1; cvt.u32.u64 %0, t; }" : "=r"(a) : "l"(p));
    return a;
}
#define LDSM4(r, addr) \
    asm volatile("ldmatrix.sync.aligned.m8n8.x4.shared.b16 {%0,%1,%2,%3}, [%4];" \
        : "=r"((r)[0]),"=r"((r)[1]),"=r"((r)[2]),"=r"((r)[3]) : "r"(addr))
#define MMAF16(d, a, b0, b1) \
    asm volatile("mma.sync.aligned.m16n8k16.row.col.f32.f16.f16.f32 " \
        "{%0,%1,%2,%3}, {%4,%5,%6,%7}, {%8,%9}, {%0,%1,%2,%3};" \
        : "+f"((d)[0]),"+f"((d)[1]),"+f"((d)[2]),"+f"((d)[3]) \
        : "r"((a)[0]),"r"((a)[1]),"r"((a)[2]),"r"((a)[3]), "r"(b0),"r"(b1))
#define CPASYNC16(dst, src) \
    asm volatile("cp.async.cg.shared.global [%0], [%1], 16;" :: "r"(dst), "l"(src))
#define CPCOMMIT() asm volatile("cp.async.commit_group;" ::: "memory")
#define CPWAIT0()  asm volatile("cp.async.wait_group 0;" ::: "memory")

// ------- threefry2x32-20 (exact JAX) -------
__device__ __forceinline__ void tf2(uint32_t k0, uint32_t k1, uint32_t x0, uint32_t x1,
                                    uint32_t& o0, uint32_t& o1) {
    uint32_t ks2 = k0 ^ k1 ^ 0x1BD11BDAu;
    x0 += k0; x1 += k1;
#define TF_R(r) { x0 += x1; x1 = (x1 << (r)) | (x1 >> (32-(r))); x1 ^= x0; }
    TF_R(13) TF_R(15) TF_R(26) TF_R(6)
    x0 += k1;  x1 += ks2 + 1u;
    TF_R(17) TF_R(29) TF_R(16) TF_R(24)
    x0 += ks2; x1 += k0 + 2u;
    TF_R(13) TF_R(15) TF_R(26) TF_R(6)
    x0 += k0;  x1 += k1 + 3u;
    TF_R(17) TF_R(29) TF_R(16) TF_R(24)
    x0 += k1;  x1 += ks2 + 4u;
    TF_R(13) TF_R(15) TF_R(26) TF_R(6)
    x0 += ks2; x1 += k0 + 5u;
#undef TF_R
    o0 = x0; o1 = x1;
}
__device__ __forceinline__ float u01(uint32_t bits) {
    return __uint_as_float((bits >> 9) | 0x3F800000u) - 1.0f;
}

// ------- prep: weight transpose + fp16 + rng -------
__global__ void __launch_bounds__(256) pinn_prep(const float* __restrict__ Wh) {
    int b = blockIdx.x;
    if (b < 320) {
        int idx = b * 256 + threadIdx.x;        // 0..81919
        int l = idx >> 14;
        int rem = idx & 16383;
        int n = rem >> 7, k = rem & 127;        // Wt[n][k] = W[k][n]
        float v = Wh[l * 16384 + k * 128 + n];
        g_Wt[(l * 128 + n) * 136 + k] = __float2half_rn(v);
    } else {
        int i = (b - 320) * 256 + threadIdx.x;  // 0..4095
        uint32_t a0, a1, b0, b1;
        tf2(0u, 22u, 0u, 2u, a0, a1);
        tf2(0u, 22u, 1u, 3u, b0, b1);
        uint32_t o0, o1;
        tf2(a0, b0, (uint32_t)i, (uint32_t)(i + 4096), o0, o1);
        g_xy[i]        = u01(o0);
        g_xy[i + 4096] = u01(o1);
        if (i < 2048) {
            uint32_t r0, r1;
            tf2(a1, b1, (uint32_t)i, (uint32_t)(i + 2048), r0, r1);
            g_zb[i]        = (float)(r0 & 1u);
            g_zb[i + 2048] = (float)(r1 & 1u);
        }
    }
}

// ------- activation jet propagation -------
__device__ __forceinline__ void act_prop(float z[NCU]) {
    const int p2a[9] = {0,0,0,1,1,1,2,2,3};
    const int p2b[9] = {1,2,3,1,2,3,2,3,3};
    const int t3a[9] = {1,2,3,1,2,3,1,2,3};
    const int t3b[9] = {1,1,1,2,2,2,3,3,3};
    const int s2s[4][4] = { {0,0,1,2}, {0,3,4,5}, {1,4,6,7}, {2,5,7,8} };

    float sv, cv;
    __sincosf(TWO_PI * z[0], &sv, &cv);
    float f0 = 0.5f * sv;
    float f1 = PI_F * cv;
    float f2 = -C2 * sv;
    float f3 = -C3 * cv;

    float d1[4], d2[9], d3[9];
#pragma unroll
    for (int i = 0; i < 4; i++) d1[i] = z[1+i];
#pragma unroll
    for (int p = 0; p < 9; p++) d2[p] = z[5+p];
#pragma unroll
    for (int q = 0; q < 9; q++) d3[q] = z[14+q];

    z[0] = f0;
#pragma unroll
    for (int i = 0; i < 4; i++) z[1+i] = f1 * d1[i];
#pragma unroll
    for (int p = 0; p < 9; p++)
        z[5+p] = f1 * d2[p] + f2 * d1[p2a[p]] * d1[p2b[p]];
#pragma unroll
    for (int q = 0; q < 9; q++) {
        int a = t3a[q], bq = t3b[q];
        float zbb = d2[s2s[bq][bq]];
        float zab = d2[s2s[a][bq]];
        z[14+q] = f1 * d3[q] + f2 * (d1[a]*zbb + 2.0f*d1[bq]*zab) + f3 * d1[a]*d1[bq]*d1[bq];
    }
}

// row scale per jet coefficient (compile-time folded under unroll)
__device__ __forceinline__ float coeff_scale(int c) {
    return (c == 0) ? 1.0f : (c < 5 ? SC1 : (c < 14 ? SC2 : SC3));
}
__device__ __forceinline__ float coeff_iscale(int c) {
    return (c == 0) ? 1.0f : (c < 5 ? IS1 : (c < 14 ? IS2 : IS3));
}

// ------- packed fp16 hi/lo write of 4 lane-adjacent values -------
__device__ __forceinline__ void write_h4(char* sm, int r, int c4, const float v[4]) {
    __half h0 = __float2half_rn(v[0]);
    __half h1 = __float2half_rn(v[1]);
    __half h2 = __float2half_rn(v[2]);
    __half h3 = __float2half_rn(v[3]);
    uint2 hi, lo;
    hi.x = (uint32_t)__half_as_ushort(h0) | ((uint32_t)__half_as_ushort(h1) << 16);
    hi.y = (uint32_t)__half_as_ushort(h2) | ((uint32_t)__half_as_ushort(h3) << 16);
    __half l0 = __float2half_rn(v[0] - __half2float(h0));
    __half l1 = __float2half_rn(v[1] - __half2float(h1));
    __half l2 = __float2half_rn(v[2] - __half2float(h2));
    __half l3 = __float2half_rn(v[3] - __half2float(h3));
    lo.x = (uint32_t)__half_as_ushort(l0) | ((uint32_t)__half_as_ushort(l1) << 16);
    lo.y = (uint32_t)__half_as_ushort(l2) | ((uint32_t)__half_as_ushort(l3) << 16);
    *(uint2*)(sm + SM_SHI + r * SROWB + c4 * 2) = hi;
    *(uint2*)(sm + SM_SLO + r * SROWB + c4 * 2) = lo;
}

// ------- 2-term fp16 GEMM via mma.sync (HMMA) -------
template<int MT>
__device__ __forceinline__ void gemm2(uint32_t smb, int row0, int col0, int lane,
                                      float acc[MT][8][4]) {
#pragma unroll
    for (int i = 0; i < MT; i++)
#pragma unroll
        for (int j = 0; j < 8; j++)
#pragma unroll
            for (int q = 0; q < 4; q++) acc[i][j][q] = 0.0f;

    int rA = (lane & 7) + ((lane >> 3) & 1) * 8;
    int kA = (lane >> 4) * 8;
    int nB = (lane & 7) + ((lane >> 4) & 1) * 8;
    int kB = ((lane >> 3) & 1) * 8;

    uint32_t aH0 = smb + SM_SHI + (uint32_t)(row0 + rA) * SROWB + kA * 2;
    uint32_t aL0 = smb + SM_SLO + (uint32_t)(row0 + rA) * SROWB + kA * 2;
    uint32_t bH0 = smb + SM_W   + (uint32_t)(col0 + nB) * SROWB + kB * 2;

#pragma unroll
    for (int kc = 0; kc < 8; kc++) {
        uint32_t ko = kc * 32;
        uint32_t aH[MT][4], aL[MT][4], bH[4][4];
#pragma unroll
        for (int i = 0; i < MT; i++) {
            LDSM4(aH[i], aH0 + (uint32_t)(i * 16) * SROWB + ko);
            LDSM4(aL[i], aL0 + (uint32_t)(i * 16) * SROWB + ko);
        }
#pragma unroll
        for (int j = 0; j < 4; j++)
            LDSM4(bH[j], bH0 + (uint32_t)(j * 16) * SROWB + ko);
#pragma unroll
        for (int i = 0; i < MT; i++)
#pragma unroll
            for (int j2 = 0; j2 < 8; j2++) {
                const uint32_t* bh = &bH[j2 >> 1][(j2 & 1) * 2];
                MMAF16(acc[i][j2], aH[i], bh[0], bh[1]);
                MMAF16(acc[i][j2], aL[i], bh[0], bh[1]);
            }
    }
}

// store accumulators as fp32 into overlay region
template<int MT>
__device__ __forceinline__ void store_accf(char* sm, int row0, int col0, int lane,
                                           float acc[MT][8][4]) {
    int g = lane >> 2, t = lane & 3;
#pragma unroll
    for (int i = 0; i < MT; i++)
#pragma unroll
        for (int j2 = 0; j2 < 8; j2++) {
            int r = row0 + i * 16 + g;
            int c = col0 + j2 * 8 + 2 * t;
            *(float2*)(sm + SM_F32 + r * FROWB + c * 4) = make_float2(acc[i][j2][0], acc[i][j2][1]);
            *(float2*)(sm + SM_F32 + (r + 8) * FROWB + c * 4) = make_float2(acc[i][j2][2], acc[i][j2][3]);
        }
}

__device__ __forceinline__ void stage_weights(char* sm, int tid, int l) {
    const char* src = (const char*)g_Wt + l * 34816;
    uint32_t dW = smem_u32(sm + SM_W);
    for (int i = tid * 16; i < 34816; i += 256 * 16)
        CPASYNC16(dW + i, src + i);
    CPCOMMIT();
}

// ------- fused tensor-core kernel -------
__global__ void __launch_bounds__(256, 1)
pinn_tc(const float* __restrict__ inputs, const float* __restrict__ y_true,
        const float* __restrict__ Win, const float* __restrict__ bin,
        const float* __restrict__ bh,  const float* __restrict__ Wo,
        const float* __restrict__ bo)
{
    extern __shared__ char sm[];
    uint32_t smb = smem_u32(sm);
    int tid = threadIdx.x;
    int bid = blockIdx.x;
    bool is_b = (bid >= NMAIN);

    float* s_bin = (float*)(sm + SM_BIN);
    float* s_bo  = (float*)(sm + SM_BO);
    float* s_bh  = (float*)(sm + SM_BH);
    float* s_Win = (float*)(sm + SM_WIN);
    float* s_Wo  = (float*)(sm + SM_WO);
    float* s_x   = (float*)(sm + SM_X);
    float* s_yt  = (float*)(sm + SM_YT);
    float* s_yc  = (float*)(sm + SM_YC);
    float* s_red = (float*)(sm + SM_YC);
    float* s_ls  = (float*)(sm + SM_LS);

    // ---- prologue ----
    if (tid < 128) s_bin[tid] = bin[tid];
    for (int i = tid; i < 640; i += 256) s_bh[i] = bh[i];
    for (int i = tid; i < 512; i += 256) { s_Win[i] = Win[i]; s_Wo[i] = Wo[i]; }
    if (tid < 4) s_bo[tid] = bo[tid];
    if (!is_b) {
        if (tid < 32) { s_x[tid] = inputs[bid*32 + tid]; s_yt[tid] = y_true[bid*32 + tid]; }
    } else {
        int gs0 = (bid - NMAIN) * 128;
        if (tid < 128) {
            int gs = gs0 + tid;
            s_x[tid*4+0] = inputs[gs*4];
            s_x[tid*4+1] = g_xy[2*gs];
            s_x[tid*4+2] = g_xy[2*gs+1];
            s_x[tid*4+3] = g_zb[gs];
        }
    }
    stage_weights(sm, tid, 0);
    __syncthreads();

    int lane = tid & 31;
    int w = tid >> 5;
    int wm = w >> 1, wn = w & 1;
    int col0 = wn * 64;
    int c4 = lane * 4;    // 4-neuron group for elementwise phases

    // ---- input layer ----
    if (!is_b) {
        int s = w;                       // warp <-> sample
        float zc[NCU][4];
#pragma unroll
        for (int n = 0; n < 4; n++) {
            int nn = c4 + n;
            float z[NCU];
            z[0] = s_bin[nn] + s_x[s*4]*s_Win[nn] + s_x[s*4+1]*s_Win[128+nn]
                 + s_x[s*4+2]*s_Win[256+nn] + s_x[s*4+3]*s_Win[384+nn];
            z[1] = s_Win[nn]; z[2] = s_Win[128+nn]; z[3] = s_Win[256+nn]; z[4] = s_Win[384+nn];
#pragma unroll
            for (int c = 5; c < NCU; c++) z[c] = 0.0f;
            act_prop(z);
#pragma unroll
            for (int c = 0; c < NCU; c++) zc[c][n] = z[c] * coeff_scale(c);
        }
#pragma unroll
        for (int c = 0; c < NCU; c++) write_h4(sm, s*NCP + c, c4, zc[c]);
        float zz[4] = {0,0,0,0};
        write_h4(sm, s*NCP + 23, c4, zz);
    } else {
        float wv0 = s_Win[c4], wv1 = s_Win[c4+1], wv2 = s_Win[c4+2], wv3 = s_Win[c4+3];
        float w10 = s_Win[128+c4], w11 = s_Win[128+c4+1], w12 = s_Win[128+c4+2], w13 = s_Win[128+c4+3];
        float w20 = s_Win[256+c4], w21 = s_Win[256+c4+1], w22 = s_Win[256+c4+2], w23 = s_Win[256+c4+3];
        float w30 = s_Win[384+c4], w31 = s_Win[384+c4+1], w32 = s_Win[384+c4+2], w33 = s_Win[384+c4+3];
        float b0 = s_bin[c4], b1 = s_bin[c4+1], b2 = s_bin[c4+2], b3 = s_bin[c4+3];
#pragma unroll
        for (int i = 0; i < 16; i++) {
            int s = w * 16 + i;
            float x0 = s_x[s*4], x1 = s_x[s*4+1], x2 = s_x[s*4+2], x3 = s_x[s*4+3];
            float v[4];
            v[0] = 0.5f * __sinf(TWO_PI * (b0 + x0*wv0 + x1*w10 + x2*w20 + x3*w30));
            v[1] = 0.5f * __sinf(TWO_PI * (b1 + x0*wv1 + x1*w11 + x2*w21 + x3*w31));
            v[2] = 0.5f * __sinf(TWO_PI * (b2 + x0*wv2 + x1*w12 + x2*w22 + x3*w32));
            v[3] = 0.5f * __sinf(TWO_PI * (b3 + x0*wv3 + x1*w13 + x2*w23 + x3*w33));
            write_h4(sm, s, c4, v);
        }
    }

    // ---- hidden layers ----
    for (int l = 0; l < NLAY; l++) {
        CPWAIT0();
        __syncthreads();

        if (!is_b) {
            float acc[3][8][4];
            gemm2<3>(smb, wm * 48, col0, lane, acc);
            __syncthreads();
            if (l < NLAY-1) stage_weights(sm, tid, l + 1);   // W region disjoint from accum
            store_accf<3>(sm, wm * 48, col0, lane, acc);
        } else {
            float acc[2][8][4];
            gemm2<2>(smb, wm * 32, col0, lane, acc);
            __syncthreads();
            if (l < NLAY-1) stage_weights(sm, tid, l + 1);
            store_accf<2>(sm, wm * 32, col0, lane, acc);
        }
        __syncthreads();

        // ---- activation (vectorized over 4 neurons) ----
        if (!is_b) {
            int s = w;
            float zc[NCU][4];
#pragma unroll
            for (int c = 0; c < NCU; c++) {
                float4 t4 = *(const float4*)(sm + SM_F32 + (s*NCP + c) * FROWB + c4 * 4);
                float isv = coeff_iscale(c);
                zc[c][0] = t4.x * isv; zc[c][1] = t4.y * isv;
                zc[c][2] = t4.z * isv; zc[c][3] = t4.w * isv;
            }
#pragma unroll
            for (int n = 0; n < 4; n++) {
                float z[NCU];
#pragma unroll
                for (int c = 0; c < NCU; c++) z[c] = zc[c][n];
                z[0] += s_bh[l*128 + c4 + n];
                act_prop(z);
#pragma unroll
                for (int c = 0; c < NCU; c++) zc[c][n] = z[c];
            }
            if (l == NLAY-1) {
                // write TRUE fp32 values in place (thread-private) for output layer
#pragma unroll
                for (int c = 0; c < NCU; c++)
                    *(float4*)(sm + SM_F32 + (s*NCP + c) * FROWB + c4 * 4)
                        = make_float4(zc[c][0], zc[c][1], zc[c][2], zc[c][3]);
            } else {
                __syncthreads();   // all fp32 reads done before fp16 overwrite
#pragma unroll
                for (int c = 0; c < NCU; c++) {
                    float sv = coeff_scale(c);
                    float vs[4] = {zc[c][0]*sv, zc[c][1]*sv, zc[c][2]*sv, zc[c][3]*sv};
                    write_h4(sm, s*NCP + c, c4, vs);
                }
                float zz[4] = {0,0,0,0};
                write_h4(sm, s*NCP + 23, c4, zz);
            }
        } else {
            float zc[16][4];
#pragma unroll
            for (int i = 0; i < 16; i++) {
                float4 t4 = *(const float4*)(sm + SM_F32 + (w*16 + i) * FROWB + c4 * 4);
                zc[i][0] = t4.x; zc[i][1] = t4.y; zc[i][2] = t4.z; zc[i][3] = t4.w;
            }
            float b0 = s_bh[l*128+c4], b1 = s_bh[l*128+c4+1], b2 = s_bh[l*128+c4+2], b3 = s_bh[l*128+c4+3];
#pragma unroll
            for (int i = 0; i < 16; i++) {
                zc[i][0] = 0.5f * __sinf(TWO_PI * (zc[i][0] + b0));
                zc[i][1] = 0.5f * __sinf(TWO_PI * (zc[i][1] + b1));
                zc[i][2] = 0.5f * __sinf(TWO_PI * (zc[i][2] + b2));
                zc[i][3] = 0.5f * __sinf(TWO_PI * (zc[i][3] + b3));
            }
            if (l == NLAY-1) {
#pragma unroll
                for (int i = 0; i < 16; i++)
                    *(float4*)(sm + SM_F32 + (w*16 + i) * FROWB + c4 * 4)
                        = make_float4(zc[i][0], zc[i][1], zc[i][2], zc[i][3]);
            } else {
                __syncthreads();
#pragma unroll
                for (int i = 0; i < 16; i++) write_h4(sm, w*16 + i, c4, zc[i]);
            }
        }
    }
    __syncthreads();

    // ---- output layer + losses ----
    if (!is_b) {
        if (tid < 192) {
            int s = tid / NCP, c = tid % NCP;
            if (c < NCU) {
                float a0 = 0, a1 = 0, a2 = 0, a3 = 0;
                const float* hr = (const float*)(sm + SM_F32 + tid * FROWB);
                for (int k = 0; k < D; k++) {
                    float h = hr[k];
                    a0 += h * s_Wo[k*4+0];
                    a1 += h * s_Wo[k*4+1];
                    a2 += h * s_Wo[k*4+2];
                    a3 += h * s_Wo[k*4+3];
                }
                if (c == 0) { a0 += s_bo[0]; a1 += s_bo[1]; a2 += s_bo[2]; a3 += s_bo[3]; }
                s_yc[(s*NCU + c)*4 + 0] = a0;
                s_yc[(s*NCU + c)*4 + 1] = a1;
                s_yc[(s*NCU + c)*4 + 2] = a2;
                s_yc[(s*NCU + c)*4 + 3] = a3;
            }
        }
        __syncthreads();
        if (tid < 8) {
            const int s = tid;
            const int s2c[4][4] = { {0,5,6,7}, {5,8,9,10}, {6,9,11,12}, {7,10,12,13} };
            auto YC = [&](int c, int o) { return s_yc[(s*NCU + c)*4 + o]; };
            auto Hc = [&](int o, int i, int j) { return YC(s2c[i][j], o); };
            auto Gc = [&](int o, int a, int b2) { return YC(14 + (b2-1)*3 + (a-1), o); };
            auto J  = [&](int o, int i) { return YC(1+i, o); };

            float u = YC(0,0), v = YC(0,1), wv = YC(0,2);
            float u_x=J(0,1), u_y=J(0,2), u_z=J(0,3);
            float v_x=J(1,1), v_y=J(1,2), v_z=J(1,3);
            float w_x=J(2,1), w_y=J(2,2), w_z=J(2,3);
            float T_t=J(3,0), T_x=J(3,1), T_y=J(3,2), T_z=J(3,3);

            float om_x = w_y - v_z, om_y = u_z - w_x, om_z = v_x - u_y;

            float NSE_u = Hc(2,2,0) - Hc(1,3,0)
                        + u*(Hc(2,2,1)-Hc(1,3,1)) + v*(Hc(2,2,2)-Hc(1,3,2)) + wv*(Hc(2,2,3)-Hc(1,3,3))
                        - om_x*u_x - om_y*u_y - om_z*u_z
                        - S_CONST*( Gc(2,2,1)-Gc(1,3,1) + Gc(2,2,2)-Gc(1,3,2) + Gc(2,2,3)-Gc(1,3,3) )
                        - T_y;
            float NSE_v = Hc(0,3,0) - Hc(2,1,0)
                        + u*(Hc(0,3,1)-Hc(2,1,1)) + v*(Hc(0,3,2)-Hc(2,1,2)) + wv*(Hc(0,3,3)-Hc(2,1,3))
                        - om_x*v_x - om_y*v_y - om_z*v_z
                        - S_CONST*( Gc(0,3,1)-Gc(2,1,1) + Gc(0,3,2)-Gc(2,1,2) + Gc(0,3,3)-Gc(2,1,3) )
                        + T_x;
            float NSE_w = Hc(1,1,0) - Hc(0,2,0)
                        + u*(Hc(1,1,1)-Hc(0,2,1)) + v*(Hc(1,1,2)-Hc(0,2,2)) + wv*(Hc(1,1,3)-Hc(0,2,3))
                        - om_x*w_x - om_y*w_y - om_z*w_z
                        - S_CONST*( Gc(1,1,1)-Gc(0,2,1) + Gc(1,1,2)-Gc(0,2,2) + Gc(1,1,3)-Gc(0,2,3) );
            float EE = T_t + u*T_x + v*T_y + wv*T_z
                     - KAPPA*( Hc(3,1,1) + Hc(3,2,2) + Hc(3,3,3) );

            float ld = 0.0f;
#pragma unroll
            for (int o = 0; o < 3; o++) {
                float dd = YC(0,o) - s_yt[s*4 + o];
                ld += dd*dd;
            }
            float conti = u_x + v_y + w_z;
            s_ls[s*4+0] = ld;
            s_ls[s*4+1] = conti*conti;
            s_ls[s*4+2] = NSE_u*NSE_u + NSE_v*NSE_v + NSE_w*NSE_w;
            s_ls[s*4+3] = EE*EE;
        }
        __syncthreads();
        if (tid == 0) {
            float a0=0, a1=0, a2=0, a3=0;
            for (int s = 0; s < 8; s++) {
                a0 += s_ls[s*4+0]; a1 += s_ls[s*4+1];
                a2 += s_ls[s*4+2]; a3 += s_ls[s*4+3];
            }
            g_part[bid*4+0] = a0; g_part[bid*4+1] = a1;
            g_part[bid*4+2] = a2; g_part[bid*4+3] = a3;
        }
    } else {
        if (tid < 128) {
            float acc = 0.0f;
            const float* hr = (const float*)(sm + SM_F32 + tid * FROWB);
            for (int k = 0; k < D; k++)
                acc += hr[k] * s_Wo[k*4+3];
            float T = acc + s_bo[3];
            float Tt = (s_x[tid*4+3] == 0.0f) ? 0.5f : -0.5f;
            float dd = Tt - T;
            s_red[tid] = dd * dd;
        }
        __syncthreads();
        if (tid == 0) {
            float a = 0.0f;
            for (int i = 0; i < 128; i++) a += s_red[i];
            g_tbpart[bid - NMAIN] = a;
        }
    }
}

// ------- final reduction -------
__global__ void __launch_bounds__(256) pinn_reduce(float* __restrict__ out) {
    __shared__ double sacc[8][5];
    int tid = threadIdx.x;
    double v[5] = {0, 0, 0, 0, 0};
    for (int i = tid; i < NMAIN; i += 256) {
        v[0] += (double)g_part[i*4+0];
        v[1] += (double)g_part[i*4+1];
        v[2] += (double)g_part[i*4+2];
        v[3] += (double)g_part[i*4+3];
    }
    if (tid < NBND) v[4] = (double)g_tbpart[tid];
#pragma unroll
    for (int o = 16; o; o >>= 1)
#pragma unroll
        for (int q = 0; q < 5; q++)
            v[q] += __shfl_down_sync(0xFFFFFFFFu, v[q], o);
    if ((tid & 31) == 0)
#pragma unroll
        for (int q = 0; q < 5; q++) sacc[tid >> 5][q] = v[q];
    __syncthreads();
    if (tid == 0) {
        double s[5] = {0, 0, 0, 0, 0};
        for (int ww = 0; ww < 8; ww++)
#pragma unroll
            for (int q = 0; q < 5; q++) s[q] += sacc[ww][q];
        double Nf = (double)N_SAMP;
        out[0] = (float)(s[0]/(3.0*Nf) + s[1]/Nf + s[2]/(3.0*Nf) + s[3]/Nf + s[4]/Nf);
    }
}

// ------- launch -------
extern "C" void kernel_launch(void* const* d_in, const int* in_sizes, int n_in,
                              void* d_out, int out_size) {
    const float* inputs = (const float*)d_in[0];
    const float* y_true = (const float*)d_in[1];
    const float* Win    = (const float*)d_in[2];
    const float* bin    = (const float*)d_in[3];
    const float* Wh     = (const float*)d_in[4];
    const float* bh     = (const float*)d_in[5];
    const float* Wo     = (const float*)d_in[6];
    const float* bo     = (const float*)d_in[7];
    float* out = (float*)d_out;

    cudaFuncSetAttribute(pinn_tc, cudaFuncAttributeMaxDynamicSharedMemorySize, SMEM_TOTAL);

    pinn_prep<<<336, 256>>>(Wh);
    pinn_tc<<<NMAIN + NBND, 256, SMEM_TOTAL>>>(inputs, y_true, Win, bin, bh, Wo, bo);
    pinn_reduce<<<1, 256>>>(out);
}

// round 7
// speedup vs baseline: 3.3306x; 1.0228x over previous
#include <cuda_runtime.h>
#include <cuda_fp16.h>
#include <cstdint>
#include <math.h>

#define N_SAMP 4096
#define D      128
#define NLAY   5
#define NCU    23
#define NCP    24

#define TWO_PI 6.2831853071795864769f
#define PI_F   3.1415926535897932385f
#define C2     19.739208802178717238f     /* 2*pi^2  */
#define C3     124.02510672119926149f     /* 4*pi^3  */
#define S_CONST 8.3666002653407556e-04f   /* sqrt(0.7/1e6) */
#define KAPPA   1.1952286093343936e-03f   /* sqrt(1/7e5)   */

#define NMAIN  1024         // main CTAs: 4 samples (96 jet rows)
#define NBND   64           // boundary CTAs: 64 samples (64 value rows)
#define NCTA   (NMAIN + NBND)

#define SROWB  272          // fp16 state/weight row stride (bytes)
#define FROWB  544          // fp32 accum row stride (bytes)

// ------- smem layout (bytes) -------
#define SM_BIN   0          // 128 f
#define SM_BO    512        // 4 f
#define SM_BH    528        // 640 f
#define SM_WIN   3088       // 512 f
#define SM_WO    5136       // 512 f
#define SM_X     7184       // 256 f
#define SM_YT    8208       // 16 f
#define SM_YC    8272       // 368 f main / 64 f red boundary / double[8][5] reduce
#define SM_LS    9744       // 16 f
#define SM_FLAG  9808       // 4 B
#define SM_W     16384      // fp16 weights: 128*272 = 34816 B
#define SM_SHI   51200      // fp16 state hi: 96*272 = 26112 B
#define SM_SLO   77312      // fp16 state lo: 26112 B
#define SM_F32   51200      // fp32 accum overlays both state tiles: 96*544 = 52224 B
#define SMEM_TOTAL 103424

// jet row scales (powers of 2; exact)
#define SC1  0.0625f
#define SC2  0.00390625f
#define SC3  2.44140625e-4f
#define IS1  16.0f
#define IS2  256.0f
#define IS3  4096.0f

// ------- global scratch -------
__device__ float g_xy[2*N_SAMP];
__device__ float g_zb[N_SAMP];
__device__ float g_part[NMAIN*4];
__device__ float g_tbpart[NBND];
__device__ unsigned int g_done;
__device__ __align__(16) __half g_Wt[NLAY*D*136];

// ------- PTX helpers -------
__device__ __forceinline__ uint32_t smem_u32(const void* p) {
    uint32_t a;
    asm("{ .reg .u64 t; cvta.to.shared.u64 t, %1; cvt.u32.u64 %0, t; }" : "=r"(a) : "l"(p));
    return a;
}
#define LDSM4(r, addr) \
    asm volatile("ldmatrix.sync.aligned.m8n8.x4.shared.b16 {%0,%1,%2,%3}, [%4];" \
        : "=r"((r)[0]),"=r"((r)[1]),"=r"((r)[2]),"=r"((r)[3]) : "r"(addr))
#define MMAF16(d, a, b0, b1) \
    asm volatile("mma.sync.aligned.m16n8k16.row.col.f32.f16.f16.f32 " \
        "{%0,%1,%2,%3}, {%4,%5,%6,%7}, {%8,%9}, {%0,%1,%2,%3};" \
        : "+f"((d)[0]),"+f"((d)[1]),"+f"((d)[2]),"+f"((d)[3]) \
        : "r"((a)[0]),"r"((a)[1]),"r"((a)[2]),"r"((a)[3]), "r"(b0),"r"(b1))
#define CPASYNC16(dst, src) \
    asm volatile("cp.async.cg.shared.global [%0], [%1], 16;" :: "r"(dst), "l"(src))
#define CPCOMMIT() asm volatile("cp.async.commit_group;" ::: "memory")
#define CPWAIT0()  asm volatile("cp.async.wait_group 0;" ::: "memory")

// ------- threefry2x32-20 (exact JAX) -------
__device__ __forceinline__ void tf2(uint32_t k0, uint32_t k1, uint32_t x0, uint32_t x1,
                                    uint32_t& o0, uint32_t& o1) {
    uint32_t ks2 = k0 ^ k1 ^ 0x1BD11BDAu;
    x0 += k0; x1 += k1;
#define TF_R(r) { x0 += x1; x1 = (x1 << (r)) | (x1 >> (32-(r))); x1 ^= x0; }
    TF_R(13) TF_R(15) TF_R(26) TF_R(6)
    x0 += k1;  x1 += ks2 + 1u;
    TF_R(17) TF_R(29) TF_R(16) TF_R(24)
    x0 += ks2; x1 += k0 + 2u;
    TF_R(13) TF_R(15) TF_R(26) TF_R(6)
    x0 += k0;  x1 += k1 + 3u;
    TF_R(17) TF_R(29) TF_R(16) TF_R(24)
    x0 += k1;  x1 += ks2 + 4u;
    TF_R(13) TF_R(15) TF_R(26) TF_R(6)
    x0 += ks2; x1 += k0 + 5u;
#undef TF_R
    o0 = x0; o1 = x1;
}
__device__ __forceinline__ float u01(uint32_t bits) {
    return __uint_as_float((bits >> 9) | 0x3F800000u) - 1.0f;
}

// ------- prep: weight transpose + fp16 + rng -------
__global__ void __launch_bounds__(256) pinn_prep(const float* __restrict__ Wh) {
    int b = blockIdx.x;
    if (b < 320) {
        int idx = b * 256 + threadIdx.x;
        int l = idx >> 14;
        int rem = idx & 16383;
        int n = rem >> 7, k = rem & 127;
        float v = Wh[l * 16384 + k * 128 + n];
        g_Wt[(l * 128 + n) * 136 + k] = __float2half_rn(v);
    } else {
        int i = (b - 320) * 256 + threadIdx.x;
        uint32_t a0, a1, b0, b1;
        tf2(0u, 22u, 0u, 2u, a0, a1);
        tf2(0u, 22u, 1u, 3u, b0, b1);
        uint32_t o0, o1;
        tf2(a0, b0, (uint32_t)i, (uint32_t)(i + 4096), o0, o1);
        g_xy[i]        = u01(o0);
        g_xy[i + 4096] = u01(o1);
        if (i < 2048) {
            uint32_t r0, r1;
            tf2(a1, b1, (uint32_t)i, (uint32_t)(i + 2048), r0, r1);
            g_zb[i]        = (float)(r0 & 1u);
            g_zb[i + 2048] = (float)(r1 & 1u);
        }
    }
}

// ------- activation jet propagation -------
__device__ __forceinline__ void act_prop(float z[NCU]) {
    const int p2a[9] = {0,0,0,1,1,1,2,2,3};
    const int p2b[9] = {1,2,3,1,2,3,2,3,3};
    const int t3a[9] = {1,2,3,1,2,3,1,2,3};
    const int t3b[9] = {1,1,1,2,2,2,3,3,3};
    const int s2s[4][4] = { {0,0,1,2}, {0,3,4,5}, {1,4,6,7}, {2,5,7,8} };

    float sv, cv;
    __sincosf(TWO_PI * z[0], &sv, &cv);
    float f0 = 0.5f * sv;
    float f1 = PI_F * cv;
    float f2 = -C2 * sv;
    float f3 = -C3 * cv;

    float d1[4], d2[9], d3[9];
#pragma unroll
    for (int i = 0; i < 4; i++) d1[i] = z[1+i];
#pragma unroll
    for (int p = 0; p < 9; p++) d2[p] = z[5+p];
#pragma unroll
    for (int q = 0; q < 9; q++) d3[q] = z[14+q];

    z[0] = f0;
#pragma unroll
    for (int i = 0; i < 4; i++) z[1+i] = f1 * d1[i];
#pragma unroll
    for (int p = 0; p < 9; p++)
        z[5+p] = f1 * d2[p] + f2 * d1[p2a[p]] * d1[p2b[p]];
#pragma unroll
    for (int q = 0; q < 9; q++) {
        int a = t3a[q], bq = t3b[q];
        float zbb = d2[s2s[bq][bq]];
        float zab = d2[s2s[a][bq]];
        z[14+q] = f1 * d3[q] + f2 * (d1[a]*zbb + 2.0f*d1[bq]*zab) + f3 * d1[a]*d1[bq]*d1[bq];
    }
}

__device__ __forceinline__ float coeff_scale(int c) {
    return (c == 0) ? 1.0f : (c < 5 ? SC1 : (c < 14 ? SC2 : SC3));
}
__device__ __forceinline__ float coeff_iscale(int c) {
    return (c == 0) ? 1.0f : (c < 5 ? IS1 : (c < 14 ? IS2 : IS3));
}

// ------- packed fp16 hi/lo writes -------
__device__ __forceinline__ void write_h2(char* sm, int r, int c2, float v0, float v1) {
    __half h0 = __float2half_rn(v0), h1 = __float2half_rn(v1);
    uint32_t hi = (uint32_t)__half_as_ushort(h0) | ((uint32_t)__half_as_ushort(h1) << 16);
    __half l0 = __float2half_rn(v0 - __half2float(h0));
    __half l1 = __float2half_rn(v1 - __half2float(h1));
    uint32_t lo = (uint32_t)__half_as_ushort(l0) | ((uint32_t)__half_as_ushort(l1) << 16);
    *(uint32_t*)(sm + SM_SHI + r * SROWB + c2 * 2) = hi;
    *(uint32_t*)(sm + SM_SLO + r * SROWB + c2 * 2) = lo;
}
__device__ __forceinline__ void write_h4(char* sm, int r, int c4, const float v[4]) {
    __half h0 = __float2half_rn(v[0]), h1 = __float2half_rn(v[1]);
    __half h2 = __float2half_rn(v[2]), h3 = __float2half_rn(v[3]);
    uint2 hi, lo;
    hi.x = (uint32_t)__half_as_ushort(h0) | ((uint32_t)__half_as_ushort(h1) << 16);
    hi.y = (uint32_t)__half_as_ushort(h2) | ((uint32_t)__half_as_ushort(h3) << 16);
    __half l0 = __float2half_rn(v[0] - __half2float(h0));
    __half l1 = __float2half_rn(v[1] - __half2float(h1));
    __half l2 = __float2half_rn(v[2] - __half2float(h2));
    __half l3 = __float2half_rn(v[3] - __half2float(h3));
    lo.x = (uint32_t)__half_as_ushort(l0) | ((uint32_t)__half_as_ushort(l1) << 16);
    lo.y = (uint32_t)__half_as_ushort(l2) | ((uint32_t)__half_as_ushort(l3) << 16);
    *(uint2*)(sm + SM_SHI + r * SROWB + c4 * 2) = hi;
    *(uint2*)(sm + SM_SLO + r * SROWB + c4 * 2) = lo;
}

// ------- 2-term fp16 GEMM: MT*16 rows x 32 cols per warp -------
template<int MT>
__device__ __forceinline__ void gemm2(uint32_t smb, int row0, int col0, int lane,
                                      float acc[MT][4][4]) {
#pragma unroll
    for (int i = 0; i < MT; i++)
#pragma unroll
        for (int j = 0; j < 4; j++)
#pragma unroll
            for (int q = 0; q < 4; q++) acc[i][j][q] = 0.0f;

    int rA = (lane & 7) + ((lane >> 3) & 1) * 8;
    int kA = (lane >> 4) * 8;
    int nB = (lane & 7) + ((lane >> 4) & 1) * 8;
    int kB = ((lane >> 3) & 1) * 8;

    uint32_t aH0 = smb + SM_SHI + (uint32_t)(row0 + rA) * SROWB + kA * 2;
    uint32_t aL0 = smb + SM_SLO + (uint32_t)(row0 + rA) * SROWB + kA * 2;
    uint32_t bH0 = smb + SM_W   + (uint32_t)(col0 + nB) * SROWB + kB * 2;

#pragma unroll
    for (int kc = 0; kc < 8; kc++) {
        uint32_t ko = kc * 32;
        uint32_t aH[MT][4], aL[MT][4], bH[2][4];
#pragma unroll
        for (int i = 0; i < MT; i++) {
            LDSM4(aH[i], aH0 + (uint32_t)(i * 16) * SROWB + ko);
            LDSM4(aL[i], aL0 + (uint32_t)(i * 16) * SROWB + ko);
        }
#pragma unroll
        for (int j = 0; j < 2; j++)
            LDSM4(bH[j], bH0 + (uint32_t)(j * 16) * SROWB + ko);
#pragma unroll
        for (int i = 0; i < MT; i++)
#pragma unroll
            for (int j2 = 0; j2 < 4; j2++) {
                const uint32_t* bh = &bH[j2 >> 1][(j2 & 1) * 2];
                MMAF16(acc[i][j2], aH[i], bh[0], bh[1]);
                MMAF16(acc[i][j2], aL[i], bh[0], bh[1]);
            }
    }
}

template<int MT>
__device__ __forceinline__ void store_accf(char* sm, int row0, int col0, int lane,
                                           float acc[MT][4][4]) {
    int g = lane >> 2, t = lane & 3;
#pragma unroll
    for (int i = 0; i < MT; i++)
#pragma unroll
        for (int j2 = 0; j2 < 4; j2++) {
            int r = row0 + i * 16 + g;
            int c = col0 + j2 * 8 + 2 * t;
            *(float2*)(sm + SM_F32 + r * FROWB + c * 4) = make_float2(acc[i][j2][0], acc[i][j2][1]);
            *(float2*)(sm + SM_F32 + (r + 8) * FROWB + c * 4) = make_float2(acc[i][j2][2], acc[i][j2][3]);
        }
}

__device__ __forceinline__ void stage_weights(char* sm, int tid, int l) {
    const char* src = (const char*)g_Wt + l * 34816;
    uint32_t dW = smem_u32(sm + SM_W);
    for (int i = tid * 16; i < 34816; i += 256 * 16)
        CPASYNC16(dW + i, src + i);
    CPCOMMIT();
}

// ------- fused tensor-core kernel (2 CTAs/SM) -------
__global__ void __launch_bounds__(256, 2)
pinn_tc(const float* __restrict__ inputs, const float* __restrict__ y_true,
        const float* __restrict__ Win, const float* __restrict__ bin,
        const float* __restrict__ bh,  const float* __restrict__ Wo,
        const float* __restrict__ bo,  float* __restrict__ out)
{
    extern __shared__ char sm[];
    uint32_t smb = smem_u32(sm);
    int tid = threadIdx.x;
    int bid = blockIdx.x;
    bool is_b = (bid >= NMAIN);

    float* s_bin = (float*)(sm + SM_BIN);
    float* s_bo  = (float*)(sm + SM_BO);
    float* s_bh  = (float*)(sm + SM_BH);
    float* s_Win = (float*)(sm + SM_WIN);
    float* s_Wo  = (float*)(sm + SM_WO);
    float* s_x   = (float*)(sm + SM_X);
    float* s_yt  = (float*)(sm + SM_YT);
    float* s_yc  = (float*)(sm + SM_YC);
    float* s_red = (float*)(sm + SM_YC);
    float* s_ls  = (float*)(sm + SM_LS);

    // ---- prologue ----
    if (tid < 128) s_bin[tid] = bin[tid];
    for (int i = tid; i < 640; i += 256) s_bh[i] = bh[i];
    for (int i = tid; i < 512; i += 256) { s_Win[i] = Win[i]; s_Wo[i] = Wo[i]; }
    if (tid < 4) s_bo[tid] = bo[tid];
    if (!is_b) {
        if (tid < 16) { s_x[tid] = inputs[bid*16 + tid]; s_yt[tid] = y_true[bid*16 + tid]; }
    } else {
        int gs0 = (bid - NMAIN) * 64;
        if (tid < 64) {
            int gs = gs0 + tid;
            s_x[tid*4+0] = inputs[gs*4];
            s_x[tid*4+1] = g_xy[2*gs];
            s_x[tid*4+2] = g_xy[2*gs+1];
            s_x[tid*4+3] = g_zb[gs];
        }
    }
    stage_weights(sm, tid, 0);
    __syncthreads();

    int lane = tid & 31;
    int w = tid >> 5;
    int wm = w >> 2, wn = w & 3;
    int col0 = wn * 32;

    // ---- input layer ----
    if (!is_b) {
        int s = tid >> 6;                // sample 0..3
        int c2 = (tid & 63) * 2;         // 2 neurons
        float zc[NCU][2];
#pragma unroll
        for (int n = 0; n < 2; n++) {
            int nn = c2 + n;
            float z[NCU];
            z[0] = s_bin[nn] + s_x[s*4]*s_Win[nn] + s_x[s*4+1]*s_Win[128+nn]
                 + s_x[s*4+2]*s_Win[256+nn] + s_x[s*4+3]*s_Win[384+nn];
            z[1] = s_Win[nn]; z[2] = s_Win[128+nn]; z[3] = s_Win[256+nn]; z[4] = s_Win[384+nn];
#pragma unroll
            for (int c = 5; c < NCU; c++) z[c] = 0.0f;
            act_prop(z);
#pragma unroll
            for (int c = 0; c < NCU; c++) zc[c][n] = z[c] * coeff_scale(c);
        }
#pragma unroll
        for (int c = 0; c < NCU; c++) write_h2(sm, s*NCP + c, c2, zc[c][0], zc[c][1]);
        write_h2(sm, s*NCP + 23, c2, 0.0f, 0.0f);
    } else {
        int s = tid >> 2;                // sample 0..63
        int q = tid & 3;                 // 32-neuron group
        float x0 = s_x[s*4], x1 = s_x[s*4+1], x2 = s_x[s*4+2], x3 = s_x[s*4+3];
#pragma unroll
        for (int i = 0; i < 8; i++) {
            float v[4];
#pragma unroll
            for (int j = 0; j < 4; j++) {
                int nn = q*32 + i*4 + j;
                float z = s_bin[nn] + x0*s_Win[nn] + x1*s_Win[128+nn]
                        + x2*s_Win[256+nn] + x3*s_Win[384+nn];
                v[j] = 0.5f * __sinf(TWO_PI * z);
            }
            write_h4(sm, s, q*32 + i*4, v);
        }
    }

    // ---- hidden layers ----
    for (int l = 0; l < NLAY; l++) {
        CPWAIT0();
        __syncthreads();

        if (!is_b) {
            float acc[3][4][4];
            gemm2<3>(smb, wm * 48, col0, lane, acc);
            __syncthreads();
            if (l < NLAY-1) stage_weights(sm, tid, l + 1);
            store_accf<3>(sm, wm * 48, col0, lane, acc);
        } else {
            float acc[2][4][4];
            gemm2<2>(smb, wm * 32, col0, lane, acc);
            __syncthreads();
            if (l < NLAY-1) stage_weights(sm, tid, l + 1);
            store_accf<2>(sm, wm * 32, col0, lane, acc);
        }
        __syncthreads();

        // ---- activation ----
        if (!is_b) {
            int s = tid >> 6;
            int c2 = (tid & 63) * 2;
            float zc[NCU][2];
#pragma unroll
            for (int c = 0; c < NCU; c++) {
                float2 t2 = *(const float2*)(sm + SM_F32 + (s*NCP + c) * FROWB + c2 * 4);
                float isv = coeff_iscale(c);
                zc[c][0] = t2.x * isv; zc[c][1] = t2.y * isv;
            }
#pragma unroll
            for (int n = 0; n < 2; n++) {
                float z[NCU];
#pragma unroll
                for (int c = 0; c < NCU; c++) z[c] = zc[c][n];
                z[0] += s_bh[l*128 + c2 + n];
                act_prop(z);
#pragma unroll
                for (int c = 0; c < NCU; c++) zc[c][n] = z[c];
            }
            if (l == NLAY-1) {
#pragma unroll
                for (int c = 0; c < NCU; c++)
                    *(float2*)(sm + SM_F32 + (s*NCP + c) * FROWB + c2 * 4)
                        = make_float2(zc[c][0], zc[c][1]);
            } else {
                __syncthreads();
#pragma unroll
                for (int c = 0; c < NCU; c++) {
                    float sv = coeff_scale(c);
                    write_h2(sm, s*NCP + c, c2, zc[c][0]*sv, zc[c][1]*sv);
                }
                write_h2(sm, s*NCP + 23, c2, 0.0f, 0.0f);
            }
        } else {
            int s = tid >> 2;
            int q = tid & 3;
            float zc[8][4];
#pragma unroll
            for (int i = 0; i < 8; i++) {
                float4 t4 = *(const float4*)(sm + SM_F32 + s * FROWB + (q*32 + i*4) * 4);
                zc[i][0] = t4.x; zc[i][1] = t4.y; zc[i][2] = t4.z; zc[i][3] = t4.w;
            }
#pragma unroll
            for (int i = 0; i < 8; i++)
#pragma unroll
                for (int j = 0; j < 4; j++)
                    zc[i][j] = 0.5f * __sinf(TWO_PI * (zc[i][j] + s_bh[l*128 + q*32 + i*4 + j]));
            if (l == NLAY-1) {
#pragma unroll
                for (int i = 0; i < 8; i++)
                    *(float4*)(sm + SM_F32 + s * FROWB + (q*32 + i*4) * 4)
                        = make_float4(zc[i][0], zc[i][1], zc[i][2], zc[i][3]);
            } else {
                __syncthreads();
#pragma unroll
                for (int i = 0; i < 8; i++) write_h4(sm, s, q*32 + i*4, zc[i]);
            }
        }
    }
    __syncthreads();

    // ---- output layer + losses ----
    if (!is_b) {
        if (tid < 96) {
            int s = tid / NCP, c = tid % NCP;
            if (c < NCU) {
                float a0 = 0, a1 = 0, a2 = 0, a3 = 0;
                const float* hr = (const float*)(sm + SM_F32 + tid * FROWB);
                for (int k = 0; k < D; k++) {
                    float h = hr[k];
                    a0 += h * s_Wo[k*4+0];
                    a1 += h * s_Wo[k*4+1];
                    a2 += h * s_Wo[k*4+2];
                    a3 += h * s_Wo[k*4+3];
                }
                if (c == 0) { a0 += s_bo[0]; a1 += s_bo[1]; a2 += s_bo[2]; a3 += s_bo[3]; }
                s_yc[(s*NCU + c)*4 + 0] = a0;
                s_yc[(s*NCU + c)*4 + 1] = a1;
                s_yc[(s*NCU + c)*4 + 2] = a2;
                s_yc[(s*NCU + c)*4 + 3] = a3;
            }
        }
        __syncthreads();
        if (tid < 4) {
            const int s = tid;
            const int s2c[4][4] = { {0,5,6,7}, {5,8,9,10}, {6,9,11,12}, {7,10,12,13} };
            auto YC = [&](int c, int o) { return s_yc[(s*NCU + c)*4 + o]; };
            auto Hc = [&](int o, int i, int j) { return YC(s2c[i][j], o); };
            auto Gc = [&](int o, int a, int b2) { return YC(14 + (b2-1)*3 + (a-1), o); };
            auto J  = [&](int o, int i) { return YC(1+i, o); };

            float u = YC(0,0), v = YC(0,1), wv = YC(0,2);
            float u_x=J(0,1), u_y=J(0,2), u_z=J(0,3);
            float v_x=J(1,1), v_y=J(1,2), v_z=J(1,3);
            float w_x=J(2,1), w_y=J(2,2), w_z=J(2,3);
            float T_t=J(3,0), T_x=J(3,1), T_y=J(3,2), T_z=J(3,3);

            float om_x = w_y - v_z, om_y = u_z - w_x, om_z = v_x - u_y;

            float NSE_u = Hc(2,2,0) - Hc(1,3,0)
                        + u*(Hc(2,2,1)-Hc(1,3,1)) + v*(Hc(2,2,2)-Hc(1,3,2)) + wv*(Hc(2,2,3)-Hc(1,3,3))
                        - om_x*u_x - om_y*u_y - om_z*u_z
                        - S_CONST*( Gc(2,2,1)-Gc(1,3,1) + Gc(2,2,2)-Gc(1,3,2) + Gc(2,2,3)-Gc(1,3,3) )
                        - T_y;
            float NSE_v = Hc(0,3,0) - Hc(2,1,0)
                        + u*(Hc(0,3,1)-Hc(2,1,1)) + v*(Hc(0,3,2)-Hc(2,1,2)) + wv*(Hc(0,3,3)-Hc(2,1,3))
                        - om_x*v_x - om_y*v_y - om_z*v_z
                        - S_CONST*( Gc(0,3,1)-Gc(2,1,1) + Gc(0,3,2)-Gc(2,1,2) + Gc(0,3,3)-Gc(2,1,3) )
                        + T_x;
            float NSE_w = Hc(1,1,0) - Hc(0,2,0)
                        + u*(Hc(1,1,1)-Hc(0,2,1)) + v*(Hc(1,1,2)-Hc(0,2,2)) + wv*(Hc(1,1,3)-Hc(0,2,3))
                        - om_x*w_x - om_y*w_y - om_z*w_z
                        - S_CONST*( Gc(1,1,1)-Gc(0,2,1) + Gc(1,1,2)-Gc(0,2,2) + Gc(1,1,3)-Gc(0,2,3) );
            float EE = T_t + u*T_x + v*T_y + wv*T_z
                     - KAPPA*( Hc(3,1,1) + Hc(3,2,2) + Hc(3,3,3) );

            float ld = 0.0f;
#pragma unroll
            for (int o = 0; o < 3; o++) {
                float dd = YC(0,o) - s_yt[s*4 + o];
                ld += dd*dd;
            }
            float conti = u_x + v_y + w_z;
            s_ls[s*4+0] = ld;
            s_ls[s*4+1] = conti*conti;
            s_ls[s*4+2] = NSE_u*NSE_u + NSE_v*NSE_v + NSE_w*NSE_w;
            s_ls[s*4+3] = EE*EE;
        }
        __syncthreads();
        if (tid == 0) {
            float a0=0, a1=0, a2=0, a3=0;
            for (int s = 0; s < 4; s++) {
                a0 += s_ls[s*4+0]; a1 += s_ls[s*4+1];
                a2 += s_ls[s*4+2]; a3 += s_ls[s*4+3];
            }
            g_part[bid*4+0] = a0; g_part[bid*4+1] = a1;
            g_part[bid*4+2] = a2; g_part[bid*4+3] = a3;
        }
    } else {
        if (tid < 64) {
            float acc = 0.0f;
            const float* hr = (const float*)(sm + SM_F32 + tid * FROWB);
            for (int k = 0; k < D; k++)
                acc += hr[k] * s_Wo[k*4+3];
            float T = acc + s_bo[3];
            float Tt = (s_x[tid*4+3] == 0.0f) ? 0.5f : -0.5f;
            float dd = Tt - T;
            s_red[tid] = dd * dd;
        }
        __syncthreads();
        if (tid == 0) {
            float a = 0.0f;
            for (int i = 0; i < 64; i++) a += s_red[i];
            g_tbpart[bid - NMAIN] = a;
        }
    }

    // ---- last-CTA final reduction ----
    __syncthreads();
    if (tid == 0) {
        __threadfence();
        unsigned int old = atomicAdd(&g_done, 1u);
        *(unsigned int*)(sm + SM_FLAG) = (old == NCTA - 1) ? 1u : 0u;
    }
    __syncthreads();
    if (*(volatile unsigned int*)(sm + SM_FLAG)) {
        double v[5] = {0, 0, 0, 0, 0};
        for (int i = tid; i < NMAIN; i += 256) {
            v[0] += (double)g_part[i*4+0];
            v[1] += (double)g_part[i*4+1];
            v[2] += (double)g_part[i*4+2];
            v[3] += (double)g_part[i*4+3];
        }
        if (tid < NBND) v[4] = (double)g_tbpart[tid];
#pragma unroll
        for (int o = 16; o; o >>= 1)
#pragma unroll
            for (int q = 0; q < 5; q++)
                v[q] += __shfl_down_sync(0xFFFFFFFFu, v[q], o);
        double* sacc = (double*)(sm + SM_YC);
        if (lane == 0)
#pragma unroll
            for (int q = 0; q < 5; q++) sacc[w*5 + q] = v[q];
        __syncthreads();
        if (tid == 0) {
            double s5[5] = {0, 0, 0, 0, 0};
            for (int ww = 0; ww < 8; ww++)
#pragma unroll
                for (int q = 0; q < 5; q++) s5[q] += sacc[ww*5 + q];
            double Nf = (double)N_SAMP;
            out[0] = (float)(s5[0]/(3.0*Nf) + s5[1]/Nf + s5[2]/(3.0*Nf) + s5[3]/Nf + s5[4]/Nf);
            g_done = 0;   // reset for next graph replay
        }
    }
}

// ------- launch -------
extern "C" void kernel_launch(void* const* d_in, const int* in_sizes, int n_in,
                              void* d_out, int out_size) {
    const float* inputs = (const float*)d_in[0];
    const float* y_true = (const float*)d_in[1];
    const float* Win    = (const float*)d_in[2];
    const float* bin    = (const float*)d_in[3];
    const float* Wh     = (const float*)d_in[4];
    const float* bh     = (const float*)d_in[5];
    const float* Wo     = (const float*)d_in[6];
    const float* bo     = (const float*)d_in[7];
    float* out = (float*)d_out;

    cudaFuncSetAttribute(pinn_tc, cudaFuncAttributeMaxDynamicSharedMemorySize, SMEM_TOTAL);

    pinn_prep<<<336, 256>>>(Wh);
    pinn_tc<<<NCTA, 256, SMEM_TOTAL>>>(inputs, y_true, Win, bin, bh, Wo, bo, out);
}

// round 8
// speedup vs baseline: 4.4297x; 1.3300x over previous
#include <cuda_runtime.h>
#include <cuda_fp16.h>
#include <cstdint>
#include <math.h>

#define N_SAMP 4096
#define D      128
#define NLAY   5
#define NCU    23
#define NCP    24

#define TWO_PI 6.2831853071795864769f
#define PI_F   3.1415926535897932385f
#define C2     19.739208802178717238f     /* 2*pi^2  */
#define C3     124.02510672119926149f     /* 4*pi^3  */
#define S_CONST 8.3666002653407556e-04f   /* sqrt(0.7/1e6) */
#define KAPPA   1.1952286093343936e-03f   /* sqrt(1/7e5)   */

#define NMAIN  1024         // main CTAs: 4 samples (96 jet rows)
#define NBND   64           // boundary CTAs: 64 samples (64 value rows)
#define NCTA   (NMAIN + NBND)

#define SROWB  272          // fp16 state/weight row stride (bytes)
#define FROWB  544          // fp32 accum row stride (bytes)

// ------- smem layout (bytes) -------
#define SM_BIN   0          // 128 f
#define SM_BO    512        // 4 f
#define SM_BH    528        // 640 f
#define SM_WIN   3088       // 512 f
#define SM_WO    5136       // 512 f
#define SM_X     7184       // 256 f
#define SM_YT    8208       // 16 f
#define SM_YC    8272       // 368 f main / 64 f red boundary / double[8][5] reduce
#define SM_LS    9744       // 16 f
#define SM_FLAG  9808       // 4 B
#define SM_W     16384      // fp16 weights: 128*272 = 34816 B
#define SM_SHI   51200      // fp16 state: 96*272 = 26112 B
#define SM_F32   51200      // fp32 accum overlay: 96*544 = 52224 B
#define SMEM_TOTAL 103424

// jet row scales (powers of 2; exact)
#define SC1  0.0625f
#define SC2  0.00390625f
#define SC3  2.44140625e-4f
#define IS1  16.0f
#define IS2  256.0f
#define IS3  4096.0f

// ------- global scratch -------
__device__ float g_xy[2*N_SAMP];
__device__ float g_zb[N_SAMP];
__device__ float g_part[NMAIN*4];
__device__ float g_tbpart[NBND];
__device__ unsigned int g_done;
__device__ __align__(16) __half g_Wt[NLAY*D*136];

// ------- PTX helpers -------
__device__ __forceinline__ uint32_t smem_u32(const void* p) {
    uint32_t a;
    asm("{ .reg .u64 t; cvta.to.shared.u64 t, %1; cvt.u32.u64 %0, t; }" : "=r"(a) : "l"(p));
    return a;
}
#define LDSM4(r, addr) \
    asm volatile("ldmatrix.sync.aligned.m8n8.x4.shared.b16 {%0,%1,%2,%3}, [%4];" \
        : "=r"((r)[0]),"=r"((r)[1]),"=r"((r)[2]),"=r"((r)[3]) : "r"(addr))
#define MMAF16(d, a, b0, b1) \
    asm volatile("mma.sync.aligned.m16n8k16.row.col.f32.f16.f16.f32 " \
        "{%0,%1,%2,%3}, {%4,%5,%6,%7}, {%8,%9}, {%0,%1,%2,%3};" \
        : "+f"((d)[0]),"+f"((d)[1]),"+f"((d)[2]),"+f"((d)[3]) \
        : "r"((a)[0]),"r"((a)[1]),"r"((a)[2]),"r"((a)[3]), "r"(b0),"r"(b1))
#define CPASYNC16(dst, src) \
    asm volatile("cp.async.cg.shared.global [%0], [%1], 16;" :: "r"(dst), "l"(src))
#define CPCOMMIT() asm volatile("cp.async.commit_group;" ::: "memory")
#define CPWAIT0()  asm volatile("cp.async.wait_group 0;" ::: "memory")

// ------- threefry2x32-20 (exact JAX) -------
__device__ __forceinline__ void tf2(uint32_t k0, uint32_t k1, uint32_t x0, uint32_t x1,
                                    uint32_t& o0, uint32_t& o1) {
    uint32_t ks2 = k0 ^ k1 ^ 0x1BD11BDAu;
    x0 += k0; x1 += k1;
#define TF_R(r) { x0 += x1; x1 = (x1 << (r)) | (x1 >> (32-(r))); x1 ^= x0; }
    TF_R(13) TF_R(15) TF_R(26) TF_R(6)
    x0 += k1;  x1 += ks2 + 1u;
    TF_R(17) TF_R(29) TF_R(16) TF_R(24)
    x0 += ks2; x1 += k0 + 2u;
    TF_R(13) TF_R(15) TF_R(26) TF_R(6)
    x0 += k0;  x1 += k1 + 3u;
    TF_R(17) TF_R(29) TF_R(16) TF_R(24)
    x0 += k1;  x1 += ks2 + 4u;
    TF_R(13) TF_R(15) TF_R(26) TF_R(6)
    x0 += ks2; x1 += k0 + 5u;
#undef TF_R
    o0 = x0; o1 = x1;
}
__device__ __forceinline__ float u01(uint32_t bits) {
    return __uint_as_float((bits >> 9) | 0x3F800000u) - 1.0f;
}

// ------- prep: weight transpose + fp16 + rng -------
__global__ void __launch_bounds__(256) pinn_prep(const float* __restrict__ Wh) {
    int b = blockIdx.x;
    if (b < 320) {
        int idx = b * 256 + threadIdx.x;
        int l = idx >> 14;
        int rem = idx & 16383;
        int n = rem >> 7, k = rem & 127;
        float v = Wh[l * 16384 + k * 128 + n];
        g_Wt[(l * 128 + n) * 136 + k] = __float2half_rn(v);
    } else {
        int i = (b - 320) * 256 + threadIdx.x;
        uint32_t a0, a1, b0, b1;
        tf2(0u, 22u, 0u, 2u, a0, a1);
        tf2(0u, 22u, 1u, 3u, b0, b1);
        uint32_t o0, o1;
        tf2(a0, b0, (uint32_t)i, (uint32_t)(i + 4096), o0, o1);
        g_xy[i]        = u01(o0);
        g_xy[i + 4096] = u01(o1);
        if (i < 2048) {
            uint32_t r0, r1;
            tf2(a1, b1, (uint32_t)i, (uint32_t)(i + 2048), r0, r1);
            g_zb[i]        = (float)(r0 & 1u);
            g_zb[i + 2048] = (float)(r1 & 1u);
        }
    }
}

// ------- activation jet propagation -------
__device__ __forceinline__ void act_prop(float z[NCU]) {
    const int p2a[9] = {0,0,0,1,1,1,2,2,3};
    const int p2b[9] = {1,2,3,1,2,3,2,3,3};
    const int t3a[9] = {1,2,3,1,2,3,1,2,3};
    const int t3b[9] = {1,1,1,2,2,2,3,3,3};
    const int s2s[4][4] = { {0,0,1,2}, {0,3,4,5}, {1,4,6,7}, {2,5,7,8} };

    float sv, cv;
    __sincosf(TWO_PI * z[0], &sv, &cv);
    float f0 = 0.5f * sv;
    float f1 = PI_F * cv;
    float f2 = -C2 * sv;
    float f3 = -C3 * cv;

    float d1[4], d2[9], d3[9];
#pragma unroll
    for (int i = 0; i < 4; i++) d1[i] = z[1+i];
#pragma unroll
    for (int p = 0; p < 9; p++) d2[p] = z[5+p];
#pragma unroll
    for (int q = 0; q < 9; q++) d3[q] = z[14+q];

    z[0] = f0;
#pragma unroll
    for (int i = 0; i < 4; i++) z[1+i] = f1 * d1[i];
#pragma unroll
    for (int p = 0; p < 9; p++)
        z[5+p] = f1 * d2[p] + f2 * d1[p2a[p]] * d1[p2b[p]];
#pragma unroll
    for (int q = 0; q < 9; q++) {
        int a = t3a[q], bq = t3b[q];
        float zbb = d2[s2s[bq][bq]];
        float zab = d2[s2s[a][bq]];
        z[14+q] = f1 * d3[q] + f2 * (d1[a]*zbb + 2.0f*d1[bq]*zab) + f3 * d1[a]*d1[bq]*d1[bq];
    }
}

__device__ __forceinline__ float coeff_scale(int c) {
    return (c == 0) ? 1.0f : (c < 5 ? SC1 : (c < 14 ? SC2 : SC3));
}
__device__ __forceinline__ float coeff_iscale(int c) {
    return (c == 0) ? 1.0f : (c < 5 ? IS1 : (c < 14 ? IS2 : IS3));
}

// ------- packed fp16 writes (single precision term) -------
__device__ __forceinline__ void write_h2(char* sm, int r, int c2, float v0, float v1) {
    __half h0 = __float2half_rn(v0), h1 = __float2half_rn(v1);
    uint32_t hi = (uint32_t)__half_as_ushort(h0) | ((uint32_t)__half_as_ushort(h1) << 16);
    *(uint32_t*)(sm + SM_SHI + r * SROWB + c2 * 2) = hi;
}
__device__ __forceinline__ void write_h4(char* sm, int r, int c4, const float v[4]) {
    __half h0 = __float2half_rn(v[0]), h1 = __float2half_rn(v[1]);
    __half h2 = __float2half_rn(v[2]), h3 = __float2half_rn(v[3]);
    uint2 hi;
    hi.x = (uint32_t)__half_as_ushort(h0) | ((uint32_t)__half_as_ushort(h1) << 16);
    hi.y = (uint32_t)__half_as_ushort(h2) | ((uint32_t)__half_as_ushort(h3) << 16);
    *(uint2*)(sm + SM_SHI + r * SROWB + c4 * 2) = hi;
}

// ------- single-term fp16 GEMM: MT*16 rows x 32 cols per warp -------
template<int MT>
__device__ __forceinline__ void gemm1(uint32_t smb, int row0, int col0, int lane,
                                      float acc[MT][4][4]) {
#pragma unroll
    for (int i = 0; i < MT; i++)
#pragma unroll
        for (int j = 0; j < 4; j++)
#pragma unroll
            for (int q = 0; q < 4; q++) acc[i][j][q] = 0.0f;

    int rA = (lane & 7) + ((lane >> 3) & 1) * 8;
    int kA = (lane >> 4) * 8;
    int nB = (lane & 7) + ((lane >> 4) & 1) * 8;
    int kB = ((lane >> 3) & 1) * 8;

    uint32_t aH0 = smb + SM_SHI + (uint32_t)(row0 + rA) * SROWB + kA * 2;
    uint32_t bH0 = smb + SM_W   + (uint32_t)(col0 + nB) * SROWB + kB * 2;

#pragma unroll
    for (int kc = 0; kc < 8; kc++) {
        uint32_t ko = kc * 32;
        uint32_t aH[MT][4], bH[2][4];
#pragma unroll
        for (int i = 0; i < MT; i++)
            LDSM4(aH[i], aH0 + (uint32_t)(i * 16) * SROWB + ko);
#pragma unroll
        for (int j = 0; j < 2; j++)
            LDSM4(bH[j], bH0 + (uint32_t)(j * 16) * SROWB + ko);
#pragma unroll
        for (int i = 0; i < MT; i++)
#pragma unroll
            for (int j2 = 0; j2 < 4; j2++) {
                const uint32_t* bh = &bH[j2 >> 1][(j2 & 1) * 2];
                MMAF16(acc[i][j2], aH[i], bh[0], bh[1]);
            }
    }
}

template<int MT>
__device__ __forceinline__ void store_accf(char* sm, int row0, int col0, int lane,
                                           float acc[MT][4][4]) {
    int g = lane >> 2, t = lane & 3;
#pragma unroll
    for (int i = 0; i < MT; i++)
#pragma unroll
        for (int j2 = 0; j2 < 4; j2++) {
            int r = row0 + i * 16 + g;
            int c = col0 + j2 * 8 + 2 * t;
            *(float2*)(sm + SM_F32 + r * FROWB + c * 4) = make_float2(acc[i][j2][0], acc[i][j2][1]);
            *(float2*)(sm + SM_F32 + (r + 8) * FROWB + c * 4) = make_float2(acc[i][j2][2], acc[i][j2][3]);
        }
}

__device__ __forceinline__ void stage_weights(char* sm, int tid, int l) {
    const char* src = (const char*)g_Wt + l * 34816;
    uint32_t dW = smem_u32(sm + SM_W);
    for (int i = tid * 16; i < 34816; i += 256 * 16)
        CPASYNC16(dW + i, src + i);
    CPCOMMIT();
}

// ------- fused tensor-core kernel (2 CTAs/SM) -------
__global__ void __launch_bounds__(256, 2)
pinn_tc(const float* __restrict__ inputs, const float* __restrict__ y_true,
        const float* __restrict__ Win, const float* __restrict__ bin,
        const float* __restrict__ bh,  const float* __restrict__ Wo,
        const float* __restrict__ bo,  float* __restrict__ out)
{
    extern __shared__ char sm[];
    uint32_t smb = smem_u32(sm);
    int tid = threadIdx.x;
    int bid = blockIdx.x;
    bool is_b = (bid >= NMAIN);

    float* s_bin = (float*)(sm + SM_BIN);
    float* s_bo  = (float*)(sm + SM_BO);
    float* s_bh  = (float*)(sm + SM_BH);
    float* s_Win = (float*)(sm + SM_WIN);
    float* s_Wo  = (float*)(sm + SM_WO);
    float* s_x   = (float*)(sm + SM_X);
    float* s_yt  = (float*)(sm + SM_YT);
    float* s_yc  = (float*)(sm + SM_YC);
    float* s_red = (float*)(sm + SM_YC);
    float* s_ls  = (float*)(sm + SM_LS);

    // ---- prologue ----
    if (tid < 128) s_bin[tid] = bin[tid];
    for (int i = tid; i < 640; i += 256) s_bh[i] = bh[i];
    for (int i = tid; i < 512; i += 256) { s_Win[i] = Win[i]; s_Wo[i] = Wo[i]; }
    if (tid < 4) s_bo[tid] = bo[tid];
    if (!is_b) {
        if (tid < 16) { s_x[tid] = inputs[bid*16 + tid]; s_yt[tid] = y_true[bid*16 + tid]; }
    } else {
        int gs0 = (bid - NMAIN) * 64;
        if (tid < 64) {
            int gs = gs0 + tid;
            s_x[tid*4+0] = inputs[gs*4];
            s_x[tid*4+1] = g_xy[2*gs];
            s_x[tid*4+2] = g_xy[2*gs+1];
            s_x[tid*4+3] = g_zb[gs];
        }
    }
    stage_weights(sm, tid, 0);
    __syncthreads();

    int lane = tid & 31;
    int w = tid >> 5;
    int wm = w >> 2, wn = w & 3;
    int col0 = wn * 32;

    // ---- input layer ----
    if (!is_b) {
        int s = tid >> 6;                // sample 0..3
        int c2 = (tid & 63) * 2;         // 2 neurons
        float zc[NCU][2];
#pragma unroll
        for (int n = 0; n < 2; n++) {
            int nn = c2 + n;
            float z[NCU];
            z[0] = s_bin[nn] + s_x[s*4]*s_Win[nn] + s_x[s*4+1]*s_Win[128+nn]
                 + s_x[s*4+2]*s_Win[256+nn] + s_x[s*4+3]*s_Win[384+nn];
            z[1] = s_Win[nn]; z[2] = s_Win[128+nn]; z[3] = s_Win[256+nn]; z[4] = s_Win[384+nn];
#pragma unroll
            for (int c = 5; c < NCU; c++) z[c] = 0.0f;
            act_prop(z);
#pragma unroll
            for (int c = 0; c < NCU; c++) zc[c][n] = z[c] * coeff_scale(c);
        }
#pragma unroll
        for (int c = 0; c < NCU; c++) write_h2(sm, s*NCP + c, c2, zc[c][0], zc[c][1]);
        write_h2(sm, s*NCP + 23, c2, 0.0f, 0.0f);
    } else {
        int s = tid >> 2;                // sample 0..63
        int q = tid & 3;                 // 32-neuron group
        float x0 = s_x[s*4], x1 = s_x[s*4+1], x2 = s_x[s*4+2], x3 = s_x[s*4+3];
#pragma unroll
        for (int i = 0; i < 8; i++) {
            float v[4];
#pragma unroll
            for (int j = 0; j < 4; j++) {
                int nn = q*32 + i*4 + j;
                float z = s_bin[nn] + x0*s_Win[nn] + x1*s_Win[128+nn]
                        + x2*s_Win[256+nn] + x3*s_Win[384+nn];
                v[j] = 0.5f * __sinf(TWO_PI * z);
            }
            write_h4(sm, s, q*32 + i*4, v);
        }
    }

    // ---- hidden layers ----
    for (int l = 0; l < NLAY; l++) {
        CPWAIT0();
        __syncthreads();

        if (!is_b) {
            float acc[3][4][4];
            gemm1<3>(smb, wm * 48, col0, lane, acc);
            __syncthreads();
            if (l < NLAY-1) stage_weights(sm, tid, l + 1);
            store_accf<3>(sm, wm * 48, col0, lane, acc);
        } else {
            float acc[2][4][4];
            gemm1<2>(smb, wm * 32, col0, lane, acc);
            __syncthreads();
            if (l < NLAY-1) stage_weights(sm, tid, l + 1);
            store_accf<2>(sm, wm * 32, col0, lane, acc);
        }
        __syncthreads();

        // ---- activation ----
        if (!is_b) {
            int s = tid >> 6;
            int c2 = (tid & 63) * 2;
            float zc[NCU][2];
#pragma unroll
            for (int c = 0; c < NCU; c++) {
                float2 t2 = *(const float2*)(sm + SM_F32 + (s*NCP + c) * FROWB + c2 * 4);
                float isv = coeff_iscale(c);
                zc[c][0] = t2.x * isv; zc[c][1] = t2.y * isv;
            }
#pragma unroll
            for (int n = 0; n < 2; n++) {
                float z[NCU];
#pragma unroll
                for (int c = 0; c < NCU; c++) z[c] = zc[c][n];
                z[0] += s_bh[l*128 + c2 + n];
                act_prop(z);
#pragma unroll
                for (int c = 0; c < NCU; c++) zc[c][n] = z[c];
            }
            if (l == NLAY-1) {
#pragma unroll
                for (int c = 0; c < NCU; c++)
                    *(float2*)(sm + SM_F32 + (s*NCP + c) * FROWB + c2 * 4)
                        = make_float2(zc[c][0], zc[c][1]);
            } else {
                __syncthreads();
#pragma unroll
                for (int c = 0; c < NCU; c++) {
                    float sv = coeff_scale(c);
                    write_h2(sm, s*NCP + c, c2, zc[c][0]*sv, zc[c][1]*sv);
                }
                write_h2(sm, s*NCP + 23, c2, 0.0f, 0.0f);
            }
        } else {
            int s = tid >> 2;
            int q = tid & 3;
            float zc[8][4];
#pragma unroll
            for (int i = 0; i < 8; i++) {
                float4 t4 = *(const float4*)(sm + SM_F32 + s * FROWB + (q*32 + i*4) * 4);
                zc[i][0] = t4.x; zc[i][1] = t4.y; zc[i][2] = t4.z; zc[i][3] = t4.w;
            }
#pragma unroll
            for (int i = 0; i < 8; i++)
#pragma unroll
                for (int j = 0; j < 4; j++)
                    zc[i][j] = 0.5f * __sinf(TWO_PI * (zc[i][j] + s_bh[l*128 + q*32 + i*4 + j]));
            if (l == NLAY-1) {
#pragma unroll
                for (int i = 0; i < 8; i++)
                    *(float4*)(sm + SM_F32 + s * FROWB + (q*32 + i*4) * 4)
                        = make_float4(zc[i][0], zc[i][1], zc[i][2], zc[i][3]);
            } else {
                __syncthreads();
#pragma unroll
                for (int i = 0; i < 8; i++) write_h4(sm, s, q*32 + i*4, zc[i]);
            }
        }
    }
    __syncthreads();

    // ---- output layer + losses ----
    if (!is_b) {
        if (tid < 96) {
            int s = tid / NCP, c = tid % NCP;
            if (c < NCU) {
                float a0 = 0, a1 = 0, a2 = 0, a3 = 0;
                const float* hr = (const float*)(sm + SM_F32 + tid * FROWB);
                for (int k = 0; k < D; k++) {
                    float h = hr[k];
                    a0 += h * s_Wo[k*4+0];
                    a1 += h * s_Wo[k*4+1];
                    a2 += h * s_Wo[k*4+2];
                    a3 += h * s_Wo[k*4+3];
                }
                if (c == 0) { a0 += s_bo[0]; a1 += s_bo[1]; a2 += s_bo[2]; a3 += s_bo[3]; }
                s_yc[(s*NCU + c)*4 + 0] = a0;
                s_yc[(s*NCU + c)*4 + 1] = a1;
                s_yc[(s*NCU + c)*4 + 2] = a2;
                s_yc[(s*NCU + c)*4 + 3] = a3;
            }
        }
        __syncthreads();
        if (tid < 4) {
            const int s = tid;
            const int s2c[4][4] = { {0,5,6,7}, {5,8,9,10}, {6,9,11,12}, {7,10,12,13} };
            auto YC = [&](int c, int o) { return s_yc[(s*NCU + c)*4 + o]; };
            auto Hc = [&](int o, int i, int j) { return YC(s2c[i][j], o); };
            auto Gc = [&](int o, int a, int b2) { return YC(14 + (b2-1)*3 + (a-1), o); };
            auto J  = [&](int o, int i) { return YC(1+i, o); };

            float u = YC(0,0), v = YC(0,1), wv = YC(0,2);
            float u_x=J(0,1), u_y=J(0,2), u_z=J(0,3);
            float v_x=J(1,1), v_y=J(1,2), v_z=J(1,3);
            float w_x=J(2,1), w_y=J(2,2), w_z=J(2,3);
            float T_t=J(3,0), T_x=J(3,1), T_y=J(3,2), T_z=J(3,3);

            float om_x = w_y - v_z, om_y = u_z - w_x, om_z = v_x - u_y;

            float NSE_u = Hc(2,2,0) - Hc(1,3,0)
                        + u*(Hc(2,2,1)-Hc(1,3,1)) + v*(Hc(2,2,2)-Hc(1,3,2)) + wv*(Hc(2,2,3)-Hc(1,3,3))
                        - om_x*u_x - om_y*u_y - om_z*u_z
                        - S_CONST*( Gc(2,2,1)-Gc(1,3,1) + Gc(2,2,2)-Gc(1,3,2) + Gc(2,2,3)-Gc(1,3,3) )
                        - T_y;
            float NSE_v = Hc(0,3,0) - Hc(2,1,0)
                        + u*(Hc(0,3,1)-Hc(2,1,1)) + v*(Hc(0,3,2)-Hc(2,1,2)) + wv*(Hc(0,3,3)-Hc(2,1,3))
                        - om_x*v_x - om_y*v_y - om_z*v_z
                        - S_CONST*( Gc(0,3,1)-Gc(2,1,1) + Gc(0,3,2)-Gc(2,1,2) + Gc(0,3,3)-Gc(2,1,3) )
                        + T_x;
            float NSE_w = Hc(1,1,0) - Hc(0,2,0)
                        + u*(Hc(1,1,1)-Hc(0,2,1)) + v*(Hc(1,1,2)-Hc(0,2,2)) + wv*(Hc(1,1,3)-Hc(0,2,3))
                        - om_x*w_x - om_y*w_y - om_z*w_z
                        - S_CONST*( Gc(1,1,1)-Gc(0,2,1) + Gc(1,1,2)-Gc(0,2,2) + Gc(1,1,3)-Gc(0,2,3) );
            float EE = T_t + u*T_x + v*T_y + wv*T_z
                     - KAPPA*( Hc(3,1,1) + Hc(3,2,2) + Hc(3,3,3) );

            float ld = 0.0f;
#pragma unroll
            for (int o = 0; o < 3; o++) {
                float dd = YC(0,o) - s_yt[s*4 + o];
                ld += dd*dd;
            }
            float conti = u_x + v_y + w_z;
            s_ls[s*4+0] = ld;
            s_ls[s*4+1] = conti*conti;
            s_ls[s*4+2] = NSE_u*NSE_u + NSE_v*NSE_v + NSE_w*NSE_w;
            s_ls[s*4+3] = EE*EE;
        }
        __syncthreads();
        if (tid == 0) {
            float a0=0, a1=0, a2=0, a3=0;
            for (int s = 0; s < 4; s++) {
                a0 += s_ls[s*4+0]; a1 += s_ls[s*4+1];
                a2 += s_ls[s*4+2]; a3 += s_ls[s*4+3];
            }
            g_part[bid*4+0] = a0; g_part[bid*4+1] = a1;
            g_part[bid*4+2] = a2; g_part[bid*4+3] = a3;
        }
    } else {
        if (tid < 64) {
            float acc = 0.0f;
            const float* hr = (const float*)(sm + SM_F32 + tid * FROWB);
            for (int k = 0; k < D; k++)
                acc += hr[k] * s_Wo[k*4+3];
            float T = acc + s_bo[3];
            float Tt = (s_x[tid*4+3] == 0.0f) ? 0.5f : -0.5f;
            float dd = Tt - T;
            s_red[tid] = dd * dd;
        }
        __syncthreads();
        if (tid == 0) {
            float a = 0.0f;
            for (int i = 0; i < 64; i++) a += s_red[i];
            g_tbpart[bid - NMAIN] = a;
        }
    }

    // ---- last-CTA final reduction ----
    __syncthreads();
    if (tid == 0) {
        __threadfence();
        unsigned int old = atomicAdd(&g_done, 1u);
        *(unsigned int*)(sm + SM_FLAG) = (old == NCTA - 1) ? 1u : 0u;
    }
    __syncthreads();
    if (*(volatile unsigned int*)(sm + SM_FLAG)) {
        double v[5] = {0, 0, 0, 0, 0};
        for (int i = tid; i < NMAIN; i += 256) {
            v[0] += (double)g_part[i*4+0];
            v[1] += (double)g_part[i*4+1];
            v[2] += (double)g_part[i*4+2];
            v[3] += (double)g_part[i*4+3];
        }
        if (tid < NBND) v[4] = (double)g_tbpart[tid];
#pragma unroll
        for (int o = 16; o; o >>= 1)
#pragma unroll
            for (int q = 0; q < 5; q++)
                v[q] += __shfl_down_sync(0xFFFFFFFFu, v[q], o);
        double* sacc = (double*)(sm + SM_YC);
        if (lane == 0)
#pragma unroll
            for (int q = 0; q < 5; q++) sacc[w*5 + q] = v[q];
        __syncthreads();
        if (tid == 0) {
            double s5[5] = {0, 0, 0, 0, 0};
            for (int ww = 0; ww < 8; ww++)
#pragma unroll
                for (int q = 0; q < 5; q++) s5[q] += sacc[ww*5 + q];
            double Nf = (double)N_SAMP;
            out[0] = (float)(s5[0]/(3.0*Nf) + s5[1]/Nf + s5[2]/(3.0*Nf) + s5[3]/Nf + s5[4]/Nf);
            g_done = 0;   // reset for next graph replay
        }
    }
}

// ------- launch -------
extern "C" void kernel_launch(void* const* d_in, const int* in_sizes, int n_in,
                              void* d_out, int out_size) {
    const float* inputs = (const float*)d_in[0];
    const float* y_true = (const float*)d_in[1];
    const float* Win    = (const float*)d_in[2];
    const float* bin    = (const float*)d_in[3];
    const float* Wh     = (const float*)d_in[4];
    const float* bh     = (const float*)d_in[5];
    const float* Wo     = (const float*)d_in[6];
    const float* bo     = (const float*)d_in[7];
    float* out = (float*)d_out;

    cudaFuncSetAttribute(pinn_tc, cudaFuncAttributeMaxDynamicSharedMemorySize, SMEM_TOTAL);

    pinn_prep<<<336, 256>>>(Wh);
    pinn_tc<<<NCTA, 256, SMEM_TOTAL>>>(inputs, y_true, Win, bin, bh, Wo, bo, out);
}